// round 14
// baseline (speedup 1.0000x reference)
#include <cuda_runtime.h>
#include <cuda_bf16.h>
#include <cuda_fp16.h>
#include <math.h>
#include <stdint.h>

#define S_LEN 8704
#define DIMV  1024
#define NH    16
#define HD    64
#define SD    4608
#define SREAL 4352
#define WIN   512
#define BQ    64
#define BK    64

// fp32 activation buffers
__device__ float g_q[S_LEN * DIMV];
__device__ float g_k[S_LEN * DIMV];

// fp16 split activations (x hi/lo for QKV GEMM); g_ahi reused for attn output
__device__ __half g_ahi[S_LEN * DIMV];
__device__ __half g_alo[S_LEN * DIMV];

// fp16 attention operands: Q split hi/lo, K single, V single
__device__ __half g_qhi[S_LEN * DIMV];
__device__ __half g_qlo[S_LEN * DIMV];
__device__ __half g_kh[S_LEN * DIMV];
__device__ __half g_vh[S_LEN * DIMV];

// fp16 transposed weights [N][K]
__device__ __half g_wqT[DIMV * DIMV];
__device__ __half g_wkT[DIMV * DIMV];
__device__ __half g_wvT[DIMV * DIMV];
__device__ __half g_woT[DIMV * DIMV];

__device__ __forceinline__ int dil2orig(int d, int p) {
    return ((p >> 8) << 9) + (d << 8) + (p & 255);
}

__device__ __forceinline__ uint32_t smem_to_u32(const void* smem_ptr) {
    uint32_t addr;
    asm("{ .reg .u64 tmp; cvta.to.shared.u64 tmp, %1; cvt.u32.u64 %0, tmp; }"
        : "=r"(addr) : "l"(smem_ptr));
    return addr;
}

// ===========================================================================
// family-generic tensor-core primitives
// ===========================================================================
__device__ __forceinline__ void ldsm4(uint32_t* r, uint32_t addr) {
    asm volatile("ldmatrix.sync.aligned.m8n8.x4.shared.b16 {%0,%1,%2,%3}, [%4];\n"
                 : "=r"(r[0]), "=r"(r[1]), "=r"(r[2]), "=r"(r[3]) : "r"(addr));
}
__device__ __forceinline__ void ldsm4t(uint32_t* r, uint32_t addr) {
    asm volatile("ldmatrix.sync.aligned.m8n8.x4.trans.shared.b16 {%0,%1,%2,%3}, [%4];\n"
                 : "=r"(r[0]), "=r"(r[1]), "=r"(r[2]), "=r"(r[3]) : "r"(addr));
}
// fp16 mma (fp32 accumulate)
__device__ __forceinline__ void mma16816h(float* c, const uint32_t* a,
                                          uint32_t b0, uint32_t b1) {
    asm volatile(
        "mma.sync.aligned.m16n8k16.row.col.f32.f16.f16.f32 "
        "{%0,%1,%2,%3}, {%4,%5,%6,%7}, {%8,%9}, {%0,%1,%2,%3};\n"
        : "+f"(c[0]), "+f"(c[1]), "+f"(c[2]), "+f"(c[3])
        : "r"(a[0]), "r"(a[1]), "r"(a[2]), "r"(a[3]), "r"(b0), "r"(b1));
}
__device__ __forceinline__ void cp_async16(uint32_t saddr, const void* gptr) {
    asm volatile("cp.async.cg.shared.global [%0], [%1], 16;\n"
                 :: "r"(saddr), "l"(gptr));
}
__device__ __forceinline__ void cp_async16z(uint32_t saddr, const void* gptr, int srcbytes) {
    asm volatile("cp.async.cg.shared.global [%0], [%1], 16, %2;\n"
                 :: "r"(saddr), "l"(gptr), "r"(srcbytes));
}
#define CP_COMMIT() asm volatile("cp.async.commit_group;\n" ::: "memory")
#define CP_WAIT0()  asm volatile("cp.async.wait_group 0;\n" ::: "memory")
#define CP_WAIT1()  asm volatile("cp.async.wait_group 1;\n" ::: "memory")

// smem tile layout: rows x 32 elem (4 x 16B chunks/row), swizzled
__device__ __forceinline__ uint32_t sw_off(int r, int c) {
    return (uint32_t)(((r >> 1) << 7) + ((r & 1) << 6) +
                      (((c ^ ((r >> 1) & 3)) & 3) << 4));
}
// attn smem tile layout: rows x 64 elem (8 x 16B chunks/row), xor swizzle
__device__ __forceinline__ uint32_t att_off(int r, int ch) {
    return (uint32_t)((r << 7) + (((ch ^ (r & 7)) & 7) << 4));
}

__device__ __forceinline__ uint32_t pack_f16x2(float a, float b) {
    __half2 t = __floats2half2_rn(a, b);
    return *(uint32_t*)&t;
}

// ===========================================================================
// split helpers
// ===========================================================================
__device__ __forceinline__ void hsplit(float f, __half& h, __half& l) {
    h = __float2half(f);
    l = __float2half(f - __half2float(h));
}

struct __align__(8) H4 { __half v[4]; };

// elementwise fp16 split: x -> hi/lo
__global__ __launch_bounds__(256) void split_kernel(
    const float* __restrict__ src, __half* __restrict__ hi,
    __half* __restrict__ lo) {
    const int idx = blockIdx.x * 256 + threadIdx.x;
    float4 v = ((const float4*)src)[idx];
    H4 h, l;
    hsplit(v.x, h.v[0], l.v[0]);
    hsplit(v.y, h.v[1], l.v[1]);
    hsplit(v.z, h.v[2], l.v[2]);
    hsplit(v.w, h.v[3], l.v[3]);
    ((H4*)hi)[idx] = h;
    ((H4*)lo)[idx] = l;
}

// transpose + fp16 convert all 4 weights; blockIdx.z selects.
__global__ __launch_bounds__(256) void wsplit_all_kernel(
    const float* __restrict__ wq, const float* __restrict__ wk,
    const float* __restrict__ wv, const float* __restrict__ wo) {
    const int z = blockIdx.z;
    const float* w = (z == 0) ? wq : (z == 1) ? wk : (z == 2) ? wv : wo;
    __half* wT = (z == 0) ? g_wqT : (z == 1) ? g_wkT : (z == 2) ? g_wvT : g_woT;

    __shared__ float t[32][33];
    const int bx = blockIdx.x << 5;
    const int by = blockIdx.y << 5;
    const int tx = threadIdx.x & 31, ty = threadIdx.x >> 5;
#pragma unroll
    for (int i = 0; i < 32; i += 8)
        t[ty + i][tx] = w[(size_t)(by + ty + i) * DIMV + bx + tx];
    __syncthreads();
#pragma unroll
    for (int i = 0; i < 32; i += 8)
        wT[(size_t)(bx + ty + i) * DIMV + by + tx] = __float2half(t[tx][ty + i]);
}

// ===========================================================================
// fp16 GEMM: C = (Ah [+ Al]) @ BhT + bias  (Alo == nullptr -> 1-pass)
// CTA 128x256, K-stage 32, 3-stage cp.async ring.
// Stage = Ahi 8K + Alo 8K + B 16K = 32KB. 8 warps x (64x64) warp tiles.
// ===========================================================================
#define STAGE_BYTES 32768
#define GEMM_SMEM_REQ (3 * STAGE_BYTES)

__device__ __forceinline__ void load_stage(
    uint32_t sbase, const __half* __restrict__ Ahi,
    const __half* __restrict__ Alo, const __half* __restrict__ B,
    int bm, int bn, int k0, int tid) {
#pragma unroll
    for (int j = 0; j < 8; j++) {
        const int chunk = tid + (j << 8);
        const int tile = chunk >> 9;          // 0=Ahi 1=Alo 2,3=B
        if (tile == 0) {
            const int idx = chunk & 511;
            const int r = idx >> 2, c = idx & 3;
            cp_async16(sbase + sw_off(r, c),
                       Ahi + (size_t)(bm + r) * DIMV + k0 + c * 8);
        } else if (tile == 1) {
            if (!Alo) continue;
            const int idx = chunk & 511;
            const int r = idx >> 2, c = idx & 3;
            cp_async16(sbase + 8192 + sw_off(r, c),
                       Alo + (size_t)(bm + r) * DIMV + k0 + c * 8);
        } else {
            const int idx = chunk & 1023;
            const int r = idx >> 2, c = idx & 3;   // r: 0..255 (N rows)
            cp_async16(sbase + 16384 + sw_off(r, c),
                       B + (size_t)(bn + r) * DIMV + k0 + c * 8);
        }
    }
}

__device__ __forceinline__ void gemm_core(
    const __half* __restrict__ Ahi, const __half* __restrict__ Alo,
    const __half* __restrict__ B,
    const float* __restrict__ bias, float* __restrict__ C,
    __half* __restrict__ Chi,
    uint32_t sb, int bm, int bn) {
    const int tid = threadIdx.x;
    const int wid = tid >> 5, lane = tid & 31;
    const int wm = (wid & 1) << 6;       // 0 | 64
    const int wn = (wid >> 1) << 6;      // 0..192
    const int lr = lane & 15;
    const int lhalf = lane >> 4;

    float acc[4][8][4];
#pragma unroll
    for (int i = 0; i < 4; i++)
#pragma unroll
        for (int j = 0; j < 8; j++)
#pragma unroll
            for (int k = 0; k < 4; k++) acc[i][j][k] = 0.f;

    load_stage(sb, Ahi, Alo, B, bm, bn, 0, tid);
    CP_COMMIT();
    load_stage(sb + STAGE_BYTES, Ahi, Alo, B, bm, bn, 32, tid);
    CP_COMMIT();

    int bufsel = 0;
    for (int s = 0; s < 32; s++) {
        if (s == 31) { CP_WAIT0(); } else { CP_WAIT1(); }
        __syncthreads();
        if (s + 2 < 32) {
            int nb = bufsel + 2;
            if (nb >= 3) nb -= 3;
            load_stage(sb + (uint32_t)nb * STAGE_BYTES, Ahi, Alo, B,
                       bm, bn, (s + 2) << 5, tid);
            CP_COMMIT();
        }

        const uint32_t buf = sb + (uint32_t)bufsel * STAGE_BYTES;
        bufsel = (bufsel == 2) ? 0 : bufsel + 1;
#pragma unroll
        for (int kk = 0; kk < 2; kk++) {
            const int cb = (kk << 1) + lhalf;
            uint32_t a[4][4], bh[4][4];
#pragma unroll
            for (int mi = 0; mi < 4; mi++)
                ldsm4(a[mi], buf + sw_off(wm + (mi << 4) + lr, cb));
#pragma unroll
            for (int np = 0; np < 4; np++)
                ldsm4(bh[np], buf + 16384 + sw_off(wn + (np << 4) + lr, cb));
            // pass 1: Ah x B
#pragma unroll
            for (int mi = 0; mi < 4; mi++)
#pragma unroll
                for (int np = 0; np < 4; np++) {
                    mma16816h(acc[mi][2 * np],     a[mi], bh[np][0], bh[np][2]);
                    mma16816h(acc[mi][2 * np + 1], a[mi], bh[np][1], bh[np][3]);
                }
            // pass 2: Al x B (skipped when Alo == nullptr)
            if (Alo) {
#pragma unroll
                for (int mi = 0; mi < 4; mi++)
                    ldsm4(a[mi], buf + 8192 + sw_off(wm + (mi << 4) + lr, cb));
#pragma unroll
                for (int mi = 0; mi < 4; mi++)
#pragma unroll
                    for (int np = 0; np < 4; np++) {
                        mma16816h(acc[mi][2 * np],     a[mi], bh[np][0], bh[np][2]);
                        mma16816h(acc[mi][2 * np + 1], a[mi], bh[np][1], bh[np][3]);
                    }
            }
        }
        // no bottom sync: next iteration's wait+sync protects stage reuse
    }

    const int crow = lane >> 2;
    const int ccol = (lane & 3) << 1;
#pragma unroll
    for (int ni = 0; ni < 8; ni++) {
        const int col = bn + wn + (ni << 3) + ccol;
        const float2 bv = *(const float2*)&bias[col];
#pragma unroll
        for (int mi = 0; mi < 4; mi++) {
            const int row = bm + wm + (mi << 4) + crow;
            const float v00 = acc[mi][ni][0] + bv.x, v01 = acc[mi][ni][1] + bv.y;
            const float v10 = acc[mi][ni][2] + bv.x, v11 = acc[mi][ni][3] + bv.y;
            if (Chi) {
                *(uint32_t*)&Chi[(size_t)row * DIMV + col] = pack_f16x2(v00, v01);
                *(uint32_t*)&Chi[(size_t)(row + 8) * DIMV + col] = pack_f16x2(v10, v11);
            } else {
                *(float2*)&C[(size_t)row * DIMV + col] = make_float2(v00, v01);
                *(float2*)&C[(size_t)(row + 8) * DIMV + col] = make_float2(v10, v11);
            }
        }
    }
}

// fused Q/K/V projection: grid (4, 68, 3). V emitted as single fp16.
__global__ __launch_bounds__(256, 1)
void gemm_qkv_kernel(const __half* __restrict__ Ahi,
                     const __half* __restrict__ Alo,
                     const float* __restrict__ bq,
                     const float* __restrict__ bk,
                     const float* __restrict__ bv) {
    extern __shared__ char smem[];
    const uint32_t sb = smem_to_u32(smem);
    const int z = blockIdx.z;
    const __half* B = (z == 0) ? g_wqT : (z == 1) ? g_wkT : g_wvT;
    const float* bias = (z == 0) ? bq : (z == 1) ? bk : bv;
    float* C = (z == 0) ? g_q : (z == 1) ? g_k : nullptr;
    __half* Chi = (z == 2) ? g_vh : nullptr;
    gemm_core(Ahi, Alo, B, bias, C, Chi, sb,
              blockIdx.y << 7, blockIdx.x << 8);
}

// output projection: A is single fp16 (attention output) -> 1-pass
__global__ __launch_bounds__(256, 1)
void gemm_out_kernel(const __half* __restrict__ Ahi,
                     const float* __restrict__ bias,
                     float* __restrict__ C) {
    extern __shared__ char smem[];
    const uint32_t sb = smem_to_u32(smem);
    gemm_core(Ahi, nullptr, g_woT, bias, C, nullptr, sb,
              blockIdx.y << 7, blockIdx.x << 8);
}

// ---------------------------------------------------------------------------
// Fused RMSNorm + RoPE + fp16 emit. blockIdx.y: 0 = Q (split hi/lo, scaled),
// 1 = K (single fp16).
// ---------------------------------------------------------------------------
__global__ __launch_bounds__(256) void normrope_split_kernel(
    const float* __restrict__ srcq, const float* __restrict__ srck,
    const float* __restrict__ gq, const float* __restrict__ gk,
    const float* __restrict__ cs, const float* __restrict__ sn,
    __half* __restrict__ qhi, __half* __restrict__ qlo,
    __half* __restrict__ kh) {
    const int s = blockIdx.x;
    const int isq = (blockIdx.y == 0);
    const float* src = isq ? srcq : srck;
    const float* g = isq ? gq : gk;
    const float scale = isq ? 0.125f : 1.0f;
    const int tid = threadIdx.x;

    float4 v = *(const float4*)&src[(size_t)s * DIMV + (tid << 2)];
    float ss = v.x * v.x + v.y * v.y + v.z * v.z + v.w * v.w;
#pragma unroll
    for (int o = 16; o; o >>= 1) ss += __shfl_xor_sync(0xffffffffu, ss, o);

    __shared__ float red[8];
    __shared__ float rtot;
    if ((tid & 31) == 0) red[tid >> 5] = ss;
    __syncthreads();
    if (tid == 0) {
        float t = 0.f;
#pragma unroll
        for (int i = 0; i < 8; i++) t += red[i];
        rtot = rsqrtf(t * (1.0f / 1024.0f) + 1e-6f);
    }
    __syncthreads();
    const float r = rtot;

    float4 gv = *(const float4*)&g[tid << 2];
    const float a0 = v.x * r * gv.x, b0 = v.y * r * gv.y;
    const float a1 = v.z * r * gv.z, b1 = v.w * r * gv.w;

    const int p0 = tid << 1;
    const int r0 = p0 & 31, r1 = (p0 + 1) & 31;
    const float c0 = cs[s * 32 + r0], s0 = sn[s * 32 + r0];
    const float c1 = cs[s * 32 + r1], s1 = sn[s * 32 + r1];

    float o0 = (a0 * c0 - b0 * s0) * scale;
    float o1 = (a0 * s0 + b0 * c0) * scale;
    float o2 = (a1 * c1 - b1 * s1) * scale;
    float o3 = (a1 * s1 + b1 * c1) * scale;

    const size_t base = (size_t)s * DIMV + (tid << 2);
    if (isq) {
        __half h0, l0, h1, l1, h2, l2, h3, l3;
        hsplit(o0, h0, l0); hsplit(o1, h1, l1);
        hsplit(o2, h2, l2); hsplit(o3, h3, l3);
        *(uint32_t*)&qhi[base] = pack_f16x2(__half2float(h0), __half2float(h1));
        *(uint32_t*)&qhi[base + 2] = pack_f16x2(__half2float(h2), __half2float(h3));
        *(uint32_t*)&qlo[base] = pack_f16x2(__half2float(l0), __half2float(l1));
        *(uint32_t*)&qlo[base + 2] = pack_f16x2(__half2float(l2), __half2float(l3));
    } else {
        *(uint32_t*)&kh[base] = pack_f16x2(o0, o1);
        *(uint32_t*)&kh[base + 2] = pack_f16x2(o2, o3);
    }
}

// ===========================================================================
// Tensor-core flash attention. QK: fp16 2-pass (Qh+Ql)·K; PV: fp16 1-pass.
// Stage = K 8KB + V 8KB = 16KB; 2 stages = 32KB.
// ===========================================================================
#define ATT_STAGE 16384
#define ATT_SMEM  (2 * ATT_STAGE)

__global__ __launch_bounds__(128)
void attn_tc_kernel(const __half* __restrict__ qhi, const __half* __restrict__ qlo,
                    const __half* __restrict__ kh, const __half* __restrict__ vh,
                    __half* __restrict__ oh) {
    extern __shared__ char smem[];
    const uint32_t sb = smem_to_u32(smem);
    const int d = blockIdx.z, h = blockIdx.y;
    const int q0 = blockIdx.x << 6;
    const int tid = threadIdx.x;
    const int warp = tid >> 5, lane = tid & 31;
    const int wq = warp << 4;
    const int lr = lane & 15, lhf = lane >> 4;
    const int qr = lane >> 2, qc = (lane & 3) << 1;

    // prologue: borrow stage smem for Q hi/lo
#pragma unroll
    for (int t = 0; t < 4; t++) {
        const int idx = tid + (t << 7);
        const int r = idx >> 3, ch = idx & 7;
        const int tok = dil2orig(d, q0 + r);
        const size_t go = (size_t)tok * DIMV + h * HD + (ch << 3);
        *(uint4*)(smem + att_off(r, ch)) = *(const uint4*)&qhi[go];
        *(uint4*)(smem + 8192 + att_off(r, ch)) = *(const uint4*)&qlo[go];
    }
    __syncthreads();

    uint32_t qh[4][4], ql[4][4];
#pragma unroll
    for (int s = 0; s < 4; s++) {
        ldsm4(qh[s], sb + att_off(wq + lr, (s << 1) + lhf));
        ldsm4(ql[s], sb + 8192 + att_off(wq + lr, (s << 1) + lhf));
    }
    __syncthreads();

    float m0 = -1e30f, m1 = -1e30f, l0 = 0.f, l1 = 0.f;
    float o[8][4];
#pragma unroll
    for (int j = 0; j < 8; j++)
#pragma unroll
        for (int k = 0; k < 4; k++) o[j][k] = 0.f;

    const int kt_lo = (q0 >= WIN) ? (q0 - WIN) : 0;
    const int kt_hi = min(SD, q0 + BQ + WIN);
    const int row0 = q0 + wq + qr, row1 = row0 + 8;

    auto stage_load = [&](int st, int kt) {
        const uint32_t stg = sb + st * ATT_STAGE;
#pragma unroll
        for (int t = 0; t < 8; t++) {
            const int cid = tid + (t << 7);
            const int buf = cid >> 9;          // 0..1
            const int idx = cid & 511;
            const int r = idx >> 3, ch = idx & 7;
            const int pk = kt + r;
            const int ok = pk < SREAL;
            const int tok = ok ? dil2orig(d, pk) : 0;
            const size_t go = ((size_t)tok * DIMV + h * HD + (ch << 3)) * 2;
            const char* src = (buf == 0) ? (const char*)kh : (const char*)vh;
            cp_async16z(stg + (buf << 13) + att_off(r, ch), src + go, ok ? 16 : 0);
        }
    };

    stage_load(0, kt_lo);
    CP_COMMIT();

    int st = 0;
    for (int kt = kt_lo; kt < kt_hi; kt += BK, st ^= 1) {
        CP_WAIT0();
        __syncthreads();
        if (kt + BK < kt_hi) { stage_load(st ^ 1, kt + BK); CP_COMMIT(); }

        const uint32_t sK = sb + st * ATT_STAGE;
        const uint32_t sV = sK + 8192;

        // --- scores: fp16 2-pass ---
        float c[8][4];
#pragma unroll
        for (int j = 0; j < 8; j++)
#pragma unroll
            for (int k = 0; k < 4; k++) c[j][k] = 0.f;

#pragma unroll
        for (int s = 0; s < 4; s++) {
#pragma unroll
            for (int g = 0; g < 4; g++) {
                uint32_t bh[4];
                ldsm4(bh, sK + att_off((g << 4) + lr, (s << 1) + lhf));
                mma16816h(c[2 * g],     qh[s], bh[0], bh[2]);
                mma16816h(c[2 * g + 1], qh[s], bh[1], bh[3]);
                mma16816h(c[2 * g],     ql[s], bh[0], bh[2]);
                mma16816h(c[2 * g + 1], ql[s], bh[1], bh[3]);
            }
        }

        const bool edge = (kt < q0 - WIN + BK) || (kt >= q0 + WIN);
        if (edge) {
#pragma unroll
            for (int j = 0; j < 8; j++) {
                const int pk = kt + (j << 3) + qc;
                if (abs(row0 - pk) > WIN)       c[j][0] = -1e9f;
                if (abs(row0 - pk - 1) > WIN)   c[j][1] = -1e9f;
                if (abs(row1 - pk) > WIN)       c[j][2] = -1e9f;
                if (abs(row1 - pk - 1) > WIN)   c[j][3] = -1e9f;
            }
        }

        // --- online softmax ---
        float tm0 = -1e30f, tm1 = -1e30f;
#pragma unroll
        for (int j = 0; j < 8; j++) {
            tm0 = fmaxf(tm0, fmaxf(c[j][0], c[j][1]));
            tm1 = fmaxf(tm1, fmaxf(c[j][2], c[j][3]));
        }
        tm0 = fmaxf(tm0, __shfl_xor_sync(0xffffffffu, tm0, 1));
        tm0 = fmaxf(tm0, __shfl_xor_sync(0xffffffffu, tm0, 2));
        tm1 = fmaxf(tm1, __shfl_xor_sync(0xffffffffu, tm1, 1));
        tm1 = fmaxf(tm1, __shfl_xor_sync(0xffffffffu, tm1, 2));

        const float mn0 = fmaxf(m0, tm0), mn1 = fmaxf(m1, tm1);
        const float cor0 = __expf(m0 - mn0), cor1 = __expf(m1 - mn1);
        m0 = mn0; m1 = mn1;

        float s0 = 0.f, s1 = 0.f;
#pragma unroll
        for (int j = 0; j < 8; j++) {
            c[j][0] = __expf(c[j][0] - mn0);
            c[j][1] = __expf(c[j][1] - mn0);
            c[j][2] = __expf(c[j][2] - mn1);
            c[j][3] = __expf(c[j][3] - mn1);
            s0 += c[j][0] + c[j][1];
            s1 += c[j][2] + c[j][3];
        }
        s0 += __shfl_xor_sync(0xffffffffu, s0, 1);
        s0 += __shfl_xor_sync(0xffffffffu, s0, 2);
        s1 += __shfl_xor_sync(0xffffffffu, s1, 1);
        s1 += __shfl_xor_sync(0xffffffffu, s1, 2);
        l0 = l0 * cor0 + s0;
        l1 = l1 * cor1 + s1;
#pragma unroll
        for (int j = 0; j < 8; j++) {
            o[j][0] *= cor0; o[j][1] *= cor0;
            o[j][2] *= cor1; o[j][3] *= cor1;
        }

        // --- PV: fp16 1-pass, P packed directly ---
#pragma unroll
        for (int s = 0; s < 4; s++) {
            uint32_t ap[4];
            ap[0] = pack_f16x2(c[2 * s][0],     c[2 * s][1]);
            ap[1] = pack_f16x2(c[2 * s][2],     c[2 * s][3]);
            ap[2] = pack_f16x2(c[2 * s + 1][0], c[2 * s + 1][1]);
            ap[3] = pack_f16x2(c[2 * s + 1][2], c[2 * s + 1][3]);
#pragma unroll
            for (int g = 0; g < 4; g++) {
                uint32_t bh[4];
                ldsm4t(bh, sV + att_off((s << 4) + lr, (g << 1) + lhf));
                mma16816h(o[2 * g],     ap, bh[0], bh[1]);
                mma16816h(o[2 * g + 1], ap, bh[2], bh[3]);
            }
        }
    }

    // epilogue: normalize, store single fp16 (feeds 1-pass out-GEMM)
    const float inv0 = 1.0f / l0, inv1 = 1.0f / l1;
    const int tok0 = dil2orig(d, row0);
    const int tok1 = dil2orig(d, row1);
#pragma unroll
    for (int j = 0; j < 8; j++) {
        const int col = h * HD + (j << 3) + qc;
        *(uint32_t*)&oh[(size_t)tok0 * DIMV + col] =
            pack_f16x2(o[j][0] * inv0, o[j][1] * inv0);
        *(uint32_t*)&oh[(size_t)tok1 * DIMV + col] =
            pack_f16x2(o[j][2] * inv1, o[j][3] * inv1);
    }
}

// ---------------------------------------------------------------------------
extern "C" void kernel_launch(void* const* d_in, const int* in_sizes, int n_in,
                              void* d_out, int out_size) {
    (void)in_sizes; (void)n_in; (void)out_size;
    const float* x  = (const float*)d_in[0];
    const float* fc = (const float*)d_in[1];
    const float* fs = (const float*)d_in[2];
    const float* wq = (const float*)d_in[3];
    const float* bq = (const float*)d_in[4];
    const float* wk = (const float*)d_in[5];
    const float* bk = (const float*)d_in[6];
    const float* wv = (const float*)d_in[7];
    const float* bv = (const float*)d_in[8];
    const float* wo = (const float*)d_in[9];
    const float* bo = (const float*)d_in[10];
    const float* gq = (const float*)d_in[11];
    const float* gk = (const float*)d_in[12];
    float* out = (float*)d_out;

    float *qb, *kb;
    cudaGetSymbolAddress((void**)&qb, g_q);
    cudaGetSymbolAddress((void**)&kb, g_k);
    __half *ahi, *alo, *vh, *qhi, *qlo, *kh;
    cudaGetSymbolAddress((void**)&ahi, g_ahi);
    cudaGetSymbolAddress((void**)&alo, g_alo);
    cudaGetSymbolAddress((void**)&vh, g_vh);
    cudaGetSymbolAddress((void**)&qhi, g_qhi);
    cudaGetSymbolAddress((void**)&qlo, g_qlo);
    cudaGetSymbolAddress((void**)&kh, g_kh);

    cudaFuncSetAttribute(gemm_qkv_kernel,
                         cudaFuncAttributeMaxDynamicSharedMemorySize, GEMM_SMEM_REQ);
    cudaFuncSetAttribute(gemm_out_kernel,
                         cudaFuncAttributeMaxDynamicSharedMemorySize, GEMM_SMEM_REQ);
    cudaFuncSetAttribute(attn_tc_kernel,
                         cudaFuncAttributeMaxDynamicSharedMemorySize, ATT_SMEM);

    wsplit_all_kernel<<<dim3(32, 32, 4), 256>>>(wq, wk, wv, wo);
    split_kernel<<<(S_LEN * DIMV) / 1024, 256>>>(x, ahi, alo);
    gemm_qkv_kernel<<<dim3(DIMV / 256, S_LEN / 128, 3), 256, GEMM_SMEM_REQ>>>(
        ahi, alo, bq, bk, bv);
    normrope_split_kernel<<<dim3(S_LEN, 2), 256>>>(qb, kb, gq, gk, fc, fs,
                                                   qhi, qlo, kh);
    attn_tc_kernel<<<dim3(SREAL / BQ, NH, 2), 128, ATT_SMEM>>>(
        qhi, qlo, kh, vh, ahi);
    gemm_out_kernel<<<dim3(DIMV / 256, S_LEN / 128), 256, GEMM_SMEM_REQ>>>(
        ahi, bo, out);
}

// round 15
// speedup vs baseline: 1.0464x; 1.0464x over previous
#include <cuda_runtime.h>
#include <cuda_bf16.h>
#include <cuda_fp16.h>
#include <math.h>
#include <stdint.h>

#define S_LEN 8704
#define DIMV  1024
#define NH    16
#define HD    64
#define SD    4608
#define SREAL 4352
#define WIN   512
#define BQ    64
#define BK    64

// fp32 activation buffers
__device__ float g_q[S_LEN * DIMV];
__device__ float g_k[S_LEN * DIMV];

// fp16 split activations (x hi/lo for QKV GEMM); g_ahi reused for attn output
__device__ __half g_ahi[S_LEN * DIMV];
__device__ __half g_alo[S_LEN * DIMV];

// fp16 attention operands: Q split hi/lo, K single, V single
__device__ __half g_qhi[S_LEN * DIMV];
__device__ __half g_qlo[S_LEN * DIMV];
__device__ __half g_kh[S_LEN * DIMV];
__device__ __half g_vh[S_LEN * DIMV];

// fp16 transposed weights [N][K]
__device__ __half g_wqT[DIMV * DIMV];
__device__ __half g_wkT[DIMV * DIMV];
__device__ __half g_wvT[DIMV * DIMV];
__device__ __half g_woT[DIMV * DIMV];

__device__ __forceinline__ int dil2orig(int d, int p) {
    return ((p >> 8) << 9) + (d << 8) + (p & 255);
}

__device__ __forceinline__ uint32_t smem_to_u32(const void* smem_ptr) {
    uint32_t addr;
    asm("{ .reg .u64 tmp; cvta.to.shared.u64 tmp, %1; cvt.u32.u64 %0, tmp; }"
        : "=r"(addr) : "l"(smem_ptr));
    return addr;
}

// ===========================================================================
// family-generic tensor-core primitives
// ===========================================================================
__device__ __forceinline__ void ldsm4(uint32_t* r, uint32_t addr) {
    asm volatile("ldmatrix.sync.aligned.m8n8.x4.shared.b16 {%0,%1,%2,%3}, [%4];\n"
                 : "=r"(r[0]), "=r"(r[1]), "=r"(r[2]), "=r"(r[3]) : "r"(addr));
}
__device__ __forceinline__ void ldsm4t(uint32_t* r, uint32_t addr) {
    asm volatile("ldmatrix.sync.aligned.m8n8.x4.trans.shared.b16 {%0,%1,%2,%3}, [%4];\n"
                 : "=r"(r[0]), "=r"(r[1]), "=r"(r[2]), "=r"(r[3]) : "r"(addr));
}
// fp16 mma (fp32 accumulate)
__device__ __forceinline__ void mma16816h(float* c, const uint32_t* a,
                                          uint32_t b0, uint32_t b1) {
    asm volatile(
        "mma.sync.aligned.m16n8k16.row.col.f32.f16.f16.f32 "
        "{%0,%1,%2,%3}, {%4,%5,%6,%7}, {%8,%9}, {%0,%1,%2,%3};\n"
        : "+f"(c[0]), "+f"(c[1]), "+f"(c[2]), "+f"(c[3])
        : "r"(a[0]), "r"(a[1]), "r"(a[2]), "r"(a[3]), "r"(b0), "r"(b1));
}
__device__ __forceinline__ void cp_async16(uint32_t saddr, const void* gptr) {
    asm volatile("cp.async.cg.shared.global [%0], [%1], 16;\n"
                 :: "r"(saddr), "l"(gptr));
}
__device__ __forceinline__ void cp_async16z(uint32_t saddr, const void* gptr, int srcbytes) {
    asm volatile("cp.async.cg.shared.global [%0], [%1], 16, %2;\n"
                 :: "r"(saddr), "l"(gptr), "r"(srcbytes));
}
#define CP_COMMIT() asm volatile("cp.async.commit_group;\n" ::: "memory")
#define CP_WAIT0()  asm volatile("cp.async.wait_group 0;\n" ::: "memory")
#define CP_WAIT1()  asm volatile("cp.async.wait_group 1;\n" ::: "memory")

// gemm smem tile layout: 128 rows x 32 elem (4 x 16B chunks/row)
__device__ __forceinline__ uint32_t sw_off(int r, int c) {
    return (uint32_t)(((r >> 1) << 7) + ((r & 1) << 6) +
                      (((c ^ ((r >> 1) & 3)) & 3) << 4));
}
// attn smem tile layout: rows x 64 elem (8 x 16B chunks/row), xor swizzle
__device__ __forceinline__ uint32_t att_off(int r, int ch) {
    return (uint32_t)((r << 7) + (((ch ^ (r & 7)) & 7) << 4));
}

__device__ __forceinline__ uint32_t pack_f16x2(float a, float b) {
    __half2 t = __floats2half2_rn(a, b);
    return *(uint32_t*)&t;
}

// ===========================================================================
// split helpers
// ===========================================================================
__device__ __forceinline__ void hsplit(float f, __half& h, __half& l) {
    h = __float2half(f);
    l = __float2half(f - __half2float(h));
}

struct __align__(8) H4 { __half v[4]; };

// elementwise fp16 split: x -> hi/lo
__global__ __launch_bounds__(256) void split_kernel(
    const float* __restrict__ src, __half* __restrict__ hi,
    __half* __restrict__ lo) {
    const int idx = blockIdx.x * 256 + threadIdx.x;
    float4 v = ((const float4*)src)[idx];
    H4 h, l;
    hsplit(v.x, h.v[0], l.v[0]);
    hsplit(v.y, h.v[1], l.v[1]);
    hsplit(v.z, h.v[2], l.v[2]);
    hsplit(v.w, h.v[3], l.v[3]);
    ((H4*)hi)[idx] = h;
    ((H4*)lo)[idx] = l;
}

// transpose + fp16 convert all 4 weights; blockIdx.z selects.
__global__ __launch_bounds__(256) void wsplit_all_kernel(
    const float* __restrict__ wq, const float* __restrict__ wk,
    const float* __restrict__ wv, const float* __restrict__ wo) {
    const int z = blockIdx.z;
    const float* w = (z == 0) ? wq : (z == 1) ? wk : (z == 2) ? wv : wo;
    __half* wT = (z == 0) ? g_wqT : (z == 1) ? g_wkT : (z == 2) ? g_wvT : g_woT;

    __shared__ float t[32][33];
    const int bx = blockIdx.x << 5;
    const int by = blockIdx.y << 5;
    const int tx = threadIdx.x & 31, ty = threadIdx.x >> 5;
#pragma unroll
    for (int i = 0; i < 32; i += 8)
        t[ty + i][tx] = w[(size_t)(by + ty + i) * DIMV + bx + tx];
    __syncthreads();
#pragma unroll
    for (int i = 0; i < 32; i += 8)
        wT[(size_t)(bx + ty + i) * DIMV + by + tx] = __float2half(t[tx][ty + i]);
}

// ===========================================================================
// fp16 GEMM: C = (Ah [+ Al]) @ BhT + bias  (Alo == nullptr -> 1-pass)
// CTA 128x128, K-stage 32, 3-stage cp.async ring (3 x 24KB smem). (R13 config)
// ===========================================================================
#define STAGE_BYTES 24576
#define GEMM_SMEM_REQ (3 * STAGE_BYTES)

__device__ __forceinline__ void load_stage(
    uint32_t sbase, const __half* __restrict__ Ahi,
    const __half* __restrict__ Alo, const __half* __restrict__ B,
    int bm, int bn, int k0, int tid) {
#pragma unroll
    for (int j = 0; j < 6; j++) {
        const int chunk = tid + (j << 8);
        const int tile = chunk >> 9;          // 0..2
        const int idx = chunk & 511;
        const int r = idx >> 2, c = idx & 3;
        const uint32_t saddr = sbase + (uint32_t)(tile << 13) + sw_off(r, c);
        const __half* gp;
        if (tile == 0)      gp = Ahi + (size_t)(bm + r) * DIMV + k0 + c * 8;
        else if (tile == 1) {
            if (!Alo) continue;
            gp = Alo + (size_t)(bm + r) * DIMV + k0 + c * 8;
        }
        else                gp = B + (size_t)(bn + r) * DIMV + k0 + c * 8;
        cp_async16(saddr, gp);
    }
}

__device__ __forceinline__ void gemm_core(
    const __half* __restrict__ Ahi, const __half* __restrict__ Alo,
    const __half* __restrict__ B,
    const float* __restrict__ bias, float* __restrict__ C,
    __half* __restrict__ Chi,
    uint32_t sb, int bm, int bn) {
    const int tid = threadIdx.x;
    const int wid = tid >> 5, lane = tid & 31;
    const int wm = (wid & 1) << 6;
    const int wn = (wid >> 1) << 5;
    const int lr = lane & 15;
    const int lhalf = lane >> 4;

    float acc[4][4][4];
#pragma unroll
    for (int i = 0; i < 4; i++)
#pragma unroll
        for (int j = 0; j < 4; j++)
#pragma unroll
            for (int k = 0; k < 4; k++) acc[i][j][k] = 0.f;

    load_stage(sb, Ahi, Alo, B, bm, bn, 0, tid);
    CP_COMMIT();
    load_stage(sb + STAGE_BYTES, Ahi, Alo, B, bm, bn, 32, tid);
    CP_COMMIT();

    int bufsel = 0;
    for (int s = 0; s < 32; s++) {
        if (s == 31) { CP_WAIT0(); } else { CP_WAIT1(); }
        __syncthreads();
        if (s + 2 < 32) {
            int nb = bufsel + 2;
            if (nb >= 3) nb -= 3;
            load_stage(sb + (uint32_t)nb * STAGE_BYTES, Ahi, Alo, B,
                       bm, bn, (s + 2) << 5, tid);
            CP_COMMIT();
        }

        const uint32_t buf = sb + (uint32_t)bufsel * STAGE_BYTES;
        bufsel = (bufsel == 2) ? 0 : bufsel + 1;
#pragma unroll
        for (int kk = 0; kk < 2; kk++) {
            const int cb = (kk << 1) + lhalf;
            uint32_t a[4][4], bh[2][4];
#pragma unroll
            for (int mi = 0; mi < 4; mi++)
                ldsm4(a[mi], buf + sw_off(wm + (mi << 4) + lr, cb));
#pragma unroll
            for (int np = 0; np < 2; np++)
                ldsm4(bh[np], buf + 16384 + sw_off(wn + (np << 4) + lr, cb));
            // pass 1: Ah x B
#pragma unroll
            for (int mi = 0; mi < 4; mi++) {
                mma16816h(acc[mi][0], a[mi], bh[0][0], bh[0][2]);
                mma16816h(acc[mi][1], a[mi], bh[0][1], bh[0][3]);
                mma16816h(acc[mi][2], a[mi], bh[1][0], bh[1][2]);
                mma16816h(acc[mi][3], a[mi], bh[1][1], bh[1][3]);
            }
            // pass 2: Al x B (skipped when Alo == nullptr)
            if (Alo) {
#pragma unroll
                for (int mi = 0; mi < 4; mi++)
                    ldsm4(a[mi], buf + 8192 + sw_off(wm + (mi << 4) + lr, cb));
#pragma unroll
                for (int mi = 0; mi < 4; mi++) {
                    mma16816h(acc[mi][0], a[mi], bh[0][0], bh[0][2]);
                    mma16816h(acc[mi][1], a[mi], bh[0][1], bh[0][3]);
                    mma16816h(acc[mi][2], a[mi], bh[1][0], bh[1][2]);
                    mma16816h(acc[mi][3], a[mi], bh[1][1], bh[1][3]);
                }
            }
        }
        // no bottom sync: next iteration's wait+sync protects stage reuse
    }

    const int crow = lane >> 2;
    const int ccol = (lane & 3) << 1;
#pragma unroll
    for (int ni = 0; ni < 4; ni++) {
        const int col = bn + wn + (ni << 3) + ccol;
        const float2 bv = *(const float2*)&bias[col];
#pragma unroll
        for (int mi = 0; mi < 4; mi++) {
            const int row = bm + wm + (mi << 4) + crow;
            const float v00 = acc[mi][ni][0] + bv.x, v01 = acc[mi][ni][1] + bv.y;
            const float v10 = acc[mi][ni][2] + bv.x, v11 = acc[mi][ni][3] + bv.y;
            if (Chi) {
                *(uint32_t*)&Chi[(size_t)row * DIMV + col] = pack_f16x2(v00, v01);
                *(uint32_t*)&Chi[(size_t)(row + 8) * DIMV + col] = pack_f16x2(v10, v11);
            } else {
                *(float2*)&C[(size_t)row * DIMV + col] = make_float2(v00, v01);
                *(float2*)&C[(size_t)(row + 8) * DIMV + col] = make_float2(v10, v11);
            }
        }
    }
}

// fused Q/K/V projection: grid (8, 68, 3). V emitted as single fp16.
__global__ __launch_bounds__(256, 2)
void gemm_qkv_kernel(const __half* __restrict__ Ahi,
                     const __half* __restrict__ Alo,
                     const float* __restrict__ bq,
                     const float* __restrict__ bk,
                     const float* __restrict__ bv) {
    extern __shared__ char smem[];
    const uint32_t sb = smem_to_u32(smem);
    const int z = blockIdx.z;
    const __half* B = (z == 0) ? g_wqT : (z == 1) ? g_wkT : g_wvT;
    const float* bias = (z == 0) ? bq : (z == 1) ? bk : bv;
    float* C = (z == 0) ? g_q : (z == 1) ? g_k : nullptr;
    __half* Chi = (z == 2) ? g_vh : nullptr;
    gemm_core(Ahi, Alo, B, bias, C, Chi, sb,
              blockIdx.y << 7, blockIdx.x << 7);
}

// output projection: A is single fp16 (attention output) -> 1-pass
__global__ __launch_bounds__(256, 2)
void gemm_out_kernel(const __half* __restrict__ Ahi,
                     const float* __restrict__ bias,
                     float* __restrict__ C) {
    extern __shared__ char smem[];
    const uint32_t sb = smem_to_u32(smem);
    gemm_core(Ahi, nullptr, g_woT, bias, C, nullptr, sb,
              blockIdx.y << 7, blockIdx.x << 7);
}

// ---------------------------------------------------------------------------
// Fused RMSNorm + RoPE + fp16 emit. blockIdx.y: 0 = Q (split hi/lo, scaled),
// 1 = K (single fp16).
// ---------------------------------------------------------------------------
__global__ __launch_bounds__(256) void normrope_split_kernel(
    const float* __restrict__ srcq, const float* __restrict__ srck,
    const float* __restrict__ gq, const float* __restrict__ gk,
    const float* __restrict__ cs, const float* __restrict__ sn,
    __half* __restrict__ qhi, __half* __restrict__ qlo,
    __half* __restrict__ kh) {
    const int s = blockIdx.x;
    const int isq = (blockIdx.y == 0);
    const float* src = isq ? srcq : srck;
    const float* g = isq ? gq : gk;
    const float scale = isq ? 0.125f : 1.0f;
    const int tid = threadIdx.x;

    float4 v = *(const float4*)&src[(size_t)s * DIMV + (tid << 2)];
    float ss = v.x * v.x + v.y * v.y + v.z * v.z + v.w * v.w;
#pragma unroll
    for (int o = 16; o; o >>= 1) ss += __shfl_xor_sync(0xffffffffu, ss, o);

    __shared__ float red[8];
    __shared__ float rtot;
    if ((tid & 31) == 0) red[tid >> 5] = ss;
    __syncthreads();
    if (tid == 0) {
        float t = 0.f;
#pragma unroll
        for (int i = 0; i < 8; i++) t += red[i];
        rtot = rsqrtf(t * (1.0f / 1024.0f) + 1e-6f);
    }
    __syncthreads();
    const float r = rtot;

    float4 gv = *(const float4*)&g[tid << 2];
    const float a0 = v.x * r * gv.x, b0 = v.y * r * gv.y;
    const float a1 = v.z * r * gv.z, b1 = v.w * r * gv.w;

    const int p0 = tid << 1;
    const int r0 = p0 & 31, r1 = (p0 + 1) & 31;
    const float c0 = cs[s * 32 + r0], s0 = sn[s * 32 + r0];
    const float c1 = cs[s * 32 + r1], s1 = sn[s * 32 + r1];

    float o0 = (a0 * c0 - b0 * s0) * scale;
    float o1 = (a0 * s0 + b0 * c0) * scale;
    float o2 = (a1 * c1 - b1 * s1) * scale;
    float o3 = (a1 * s1 + b1 * c1) * scale;

    const size_t base = (size_t)s * DIMV + (tid << 2);
    if (isq) {
        __half h0, l0, h1, l1, h2, l2, h3, l3;
        hsplit(o0, h0, l0); hsplit(o1, h1, l1);
        hsplit(o2, h2, l2); hsplit(o3, h3, l3);
        *(uint32_t*)&qhi[base] = pack_f16x2(__half2float(h0), __half2float(h1));
        *(uint32_t*)&qhi[base + 2] = pack_f16x2(__half2float(h2), __half2float(h3));
        *(uint32_t*)&qlo[base] = pack_f16x2(__half2float(l0), __half2float(l1));
        *(uint32_t*)&qlo[base + 2] = pack_f16x2(__half2float(l2), __half2float(l3));
    } else {
        *(uint32_t*)&kh[base] = pack_f16x2(o0, o1);
        *(uint32_t*)&kh[base + 2] = pack_f16x2(o2, o3);
    }
}

// ===========================================================================
// Tensor-core flash attention. QK: fp16 2-pass (Qh+Ql)·K; PV: fp16 1-pass.
// 3-stage cp.async ring: stage = K 8KB + V 8KB = 16KB; 3 stages = 48KB.
// ===========================================================================
#define ATT_STAGE 16384
#define ATT_SMEM  (3 * ATT_STAGE)

__global__ __launch_bounds__(128)
void attn_tc_kernel(const __half* __restrict__ qhi, const __half* __restrict__ qlo,
                    const __half* __restrict__ kh, const __half* __restrict__ vh,
                    __half* __restrict__ oh) {
    extern __shared__ char smem[];
    const uint32_t sb = smem_to_u32(smem);
    const int d = blockIdx.z, h = blockIdx.y;
    const int q0 = blockIdx.x << 6;
    const int tid = threadIdx.x;
    const int warp = tid >> 5, lane = tid & 31;
    const int wq = warp << 4;
    const int lr = lane & 15, lhf = lane >> 4;
    const int qr = lane >> 2, qc = (lane & 3) << 1;

    // prologue: borrow stage-0 smem for Q hi/lo (16KB)
#pragma unroll
    for (int t = 0; t < 4; t++) {
        const int idx = tid + (t << 7);
        const int r = idx >> 3, ch = idx & 7;
        const int tok = dil2orig(d, q0 + r);
        const size_t go = (size_t)tok * DIMV + h * HD + (ch << 3);
        *(uint4*)(smem + att_off(r, ch)) = *(const uint4*)&qhi[go];
        *(uint4*)(smem + 8192 + att_off(r, ch)) = *(const uint4*)&qlo[go];
    }
    __syncthreads();

    uint32_t qh[4][4], ql[4][4];
#pragma unroll
    for (int s = 0; s < 4; s++) {
        ldsm4(qh[s], sb + att_off(wq + lr, (s << 1) + lhf));
        ldsm4(ql[s], sb + 8192 + att_off(wq + lr, (s << 1) + lhf));
    }
    __syncthreads();

    float m0 = -1e30f, m1 = -1e30f, l0 = 0.f, l1 = 0.f;
    float o[8][4];
#pragma unroll
    for (int j = 0; j < 8; j++)
#pragma unroll
        for (int k = 0; k < 4; k++) o[j][k] = 0.f;

    const int kt_lo = (q0 >= WIN) ? (q0 - WIN) : 0;
    const int kt_hi = min(SD, q0 + BQ + WIN);
    const int nt = (kt_hi - kt_lo + BK - 1) / BK;
    const int row0 = q0 + wq + qr, row1 = row0 + 8;

    auto stage_load = [&](int st, int kt) {
        const uint32_t stg = sb + (uint32_t)st * ATT_STAGE;
#pragma unroll
        for (int t = 0; t < 8; t++) {
            const int cid = tid + (t << 7);
            const int buf = cid >> 9;          // 0..1
            const int idx = cid & 511;
            const int r = idx >> 3, ch = idx & 7;
            const int pk = kt + r;
            const int ok = pk < SREAL;
            const int tok = ok ? dil2orig(d, pk) : 0;
            const size_t go = ((size_t)tok * DIMV + h * HD + (ch << 3)) * 2;
            const char* src = (buf == 0) ? (const char*)kh : (const char*)vh;
            cp_async16z(stg + (buf << 13) + att_off(r, ch), src + go, ok ? 16 : 0);
        }
    };

    stage_load(0, kt_lo);
    CP_COMMIT();
    if (nt > 1) { stage_load(1, kt_lo + BK); CP_COMMIT(); }

    int bufsel = 0;
    for (int i = 0; i < nt; i++) {
        const int kt = kt_lo + i * BK;
        if (i >= nt - 2) { CP_WAIT0(); } else { CP_WAIT1(); }
        __syncthreads();
        if (i + 2 < nt) {
            int nb = bufsel + 2;
            if (nb >= 3) nb -= 3;
            stage_load(nb, kt + 2 * BK);
            CP_COMMIT();
        }

        const uint32_t sK = sb + (uint32_t)bufsel * ATT_STAGE;
        const uint32_t sV = sK + 8192;
        bufsel = (bufsel == 2) ? 0 : bufsel + 1;

        // --- scores: fp16 2-pass ---
        float c[8][4];
#pragma unroll
        for (int j = 0; j < 8; j++)
#pragma unroll
            for (int k = 0; k < 4; k++) c[j][k] = 0.f;

#pragma unroll
        for (int s = 0; s < 4; s++) {
#pragma unroll
            for (int g = 0; g < 4; g++) {
                uint32_t bh[4];
                ldsm4(bh, sK + att_off((g << 4) + lr, (s << 1) + lhf));
                mma16816h(c[2 * g],     qh[s], bh[0], bh[2]);
                mma16816h(c[2 * g + 1], qh[s], bh[1], bh[3]);
                mma16816h(c[2 * g],     ql[s], bh[0], bh[2]);
                mma16816h(c[2 * g + 1], ql[s], bh[1], bh[3]);
            }
        }

        const bool edge = (kt < q0 - WIN + BK) || (kt >= q0 + WIN);
        if (edge) {
#pragma unroll
            for (int j = 0; j < 8; j++) {
                const int pk = kt + (j << 3) + qc;
                if (abs(row0 - pk) > WIN)       c[j][0] = -1e9f;
                if (abs(row0 - pk - 1) > WIN)   c[j][1] = -1e9f;
                if (abs(row1 - pk) > WIN)       c[j][2] = -1e9f;
                if (abs(row1 - pk - 1) > WIN)   c[j][3] = -1e9f;
            }
        }

        // --- online softmax ---
        float tm0 = -1e30f, tm1 = -1e30f;
#pragma unroll
        for (int j = 0; j < 8; j++) {
            tm0 = fmaxf(tm0, fmaxf(c[j][0], c[j][1]));
            tm1 = fmaxf(tm1, fmaxf(c[j][2], c[j][3]));
        }
        tm0 = fmaxf(tm0, __shfl_xor_sync(0xffffffffu, tm0, 1));
        tm0 = fmaxf(tm0, __shfl_xor_sync(0xffffffffu, tm0, 2));
        tm1 = fmaxf(tm1, __shfl_xor_sync(0xffffffffu, tm1, 1));
        tm1 = fmaxf(tm1, __shfl_xor_sync(0xffffffffu, tm1, 2));

        const float mn0 = fmaxf(m0, tm0), mn1 = fmaxf(m1, tm1);
        const float cor0 = __expf(m0 - mn0), cor1 = __expf(m1 - mn1);
        m0 = mn0; m1 = mn1;

        float s0 = 0.f, s1 = 0.f;
#pragma unroll
        for (int j = 0; j < 8; j++) {
            c[j][0] = __expf(c[j][0] - mn0);
            c[j][1] = __expf(c[j][1] - mn0);
            c[j][2] = __expf(c[j][2] - mn1);
            c[j][3] = __expf(c[j][3] - mn1);
            s0 += c[j][0] + c[j][1];
            s1 += c[j][2] + c[j][3];
        }
        s0 += __shfl_xor_sync(0xffffffffu, s0, 1);
        s0 += __shfl_xor_sync(0xffffffffu, s0, 2);
        s1 += __shfl_xor_sync(0xffffffffu, s1, 1);
        s1 += __shfl_xor_sync(0xffffffffu, s1, 2);
        l0 = l0 * cor0 + s0;
        l1 = l1 * cor1 + s1;
#pragma unroll
        for (int j = 0; j < 8; j++) {
            o[j][0] *= cor0; o[j][1] *= cor0;
            o[j][2] *= cor1; o[j][3] *= cor1;
        }

        // --- PV: fp16 1-pass, P packed directly ---
#pragma unroll
        for (int s = 0; s < 4; s++) {
            uint32_t ap[4];
            ap[0] = pack_f16x2(c[2 * s][0],     c[2 * s][1]);
            ap[1] = pack_f16x2(c[2 * s][2],     c[2 * s][3]);
            ap[2] = pack_f16x2(c[2 * s + 1][0], c[2 * s + 1][1]);
            ap[3] = pack_f16x2(c[2 * s + 1][2], c[2 * s + 1][3]);
#pragma unroll
            for (int g = 0; g < 4; g++) {
                uint32_t bh[4];
                ldsm4t(bh, sV + att_off((s << 4) + lr, (g << 1) + lhf));
                mma16816h(o[2 * g],     ap, bh[0], bh[1]);
                mma16816h(o[2 * g + 1], ap, bh[2], bh[3]);
            }
        }
    }

    // epilogue: normalize, store single fp16 (feeds 1-pass out-GEMM)
    const float inv0 = 1.0f / l0, inv1 = 1.0f / l1;
    const int tok0 = dil2orig(d, row0);
    const int tok1 = dil2orig(d, row1);
#pragma unroll
    for (int j = 0; j < 8; j++) {
        const int col = h * HD + (j << 3) + qc;
        *(uint32_t*)&oh[(size_t)tok0 * DIMV + col] =
            pack_f16x2(o[j][0] * inv0, o[j][1] * inv0);
        *(uint32_t*)&oh[(size_t)tok1 * DIMV + col] =
            pack_f16x2(o[j][2] * inv1, o[j][3] * inv1);
    }
}

// ---------------------------------------------------------------------------
extern "C" void kernel_launch(void* const* d_in, const int* in_sizes, int n_in,
                              void* d_out, int out_size) {
    (void)in_sizes; (void)n_in; (void)out_size;
    const float* x  = (const float*)d_in[0];
    const float* fc = (const float*)d_in[1];
    const float* fs = (const float*)d_in[2];
    const float* wq = (const float*)d_in[3];
    const float* bq = (const float*)d_in[4];
    const float* wk = (const float*)d_in[5];
    const float* bk = (const float*)d_in[6];
    const float* wv = (const float*)d_in[7];
    const float* bv = (const float*)d_in[8];
    const float* wo = (const float*)d_in[9];
    const float* bo = (const float*)d_in[10];
    const float* gq = (const float*)d_in[11];
    const float* gk = (const float*)d_in[12];
    float* out = (float*)d_out;

    float *qb, *kb;
    cudaGetSymbolAddress((void**)&qb, g_q);
    cudaGetSymbolAddress((void**)&kb, g_k);
    __half *ahi, *alo, *vh, *qhi, *qlo, *kh;
    cudaGetSymbolAddress((void**)&ahi, g_ahi);
    cudaGetSymbolAddress((void**)&alo, g_alo);
    cudaGetSymbolAddress((void**)&vh, g_vh);
    cudaGetSymbolAddress((void**)&qhi, g_qhi);
    cudaGetSymbolAddress((void**)&qlo, g_qlo);
    cudaGetSymbolAddress((void**)&kh, g_kh);

    cudaFuncSetAttribute(gemm_qkv_kernel,
                         cudaFuncAttributeMaxDynamicSharedMemorySize, GEMM_SMEM_REQ);
    cudaFuncSetAttribute(gemm_out_kernel,
                         cudaFuncAttributeMaxDynamicSharedMemorySize, GEMM_SMEM_REQ);
    cudaFuncSetAttribute(attn_tc_kernel,
                         cudaFuncAttributeMaxDynamicSharedMemorySize, ATT_SMEM);

    wsplit_all_kernel<<<dim3(32, 32, 4), 256>>>(wq, wk, wv, wo);
    split_kernel<<<(S_LEN * DIMV) / 1024, 256>>>(x, ahi, alo);
    gemm_qkv_kernel<<<dim3(DIMV / 128, S_LEN / 128, 3), 256, GEMM_SMEM_REQ>>>(
        ahi, alo, bq, bk, bv);
    normrope_split_kernel<<<dim3(S_LEN, 2), 256>>>(qb, kb, gq, gk, fc, fs,
                                                   qhi, qlo, kh);
    attn_tc_kernel<<<dim3(SREAL / BQ, NH, 2), 128, ATT_SMEM>>>(
        qhi, qlo, kh, vh, ahi);
    gemm_out_kernel<<<dim3(DIMV / 128, S_LEN / 128), 256, GEMM_SMEM_REQ>>>(
        ahi, bo, out);
}

// round 16
// speedup vs baseline: 1.0952x; 1.0467x over previous
#include <cuda_runtime.h>
#include <cuda_bf16.h>
#include <cuda_fp16.h>
#include <math.h>
#include <stdint.h>

#define S_LEN 8704
#define DIMV  1024
#define NH    16
#define HD    64
#define SD    4608
#define SREAL 4352
#define WIN   512
#define BQ    64
#define BK    64

// fp32 activation buffers
__device__ float g_q[S_LEN * DIMV];
__device__ float g_k[S_LEN * DIMV];

// fp16 split activations (x hi/lo for QKV GEMM); g_ahi reused for attn output
__device__ __half g_ahi[S_LEN * DIMV];
__device__ __half g_alo[S_LEN * DIMV];

// fp16 attention operands: Q, K, V all single fp16
__device__ __half g_qh[S_LEN * DIMV];
__device__ __half g_kh[S_LEN * DIMV];
__device__ __half g_vh[S_LEN * DIMV];

// fp16 transposed weights [N][K]
__device__ __half g_wqT[DIMV * DIMV];
__device__ __half g_wkT[DIMV * DIMV];
__device__ __half g_wvT[DIMV * DIMV];
__device__ __half g_woT[DIMV * DIMV];

__device__ __forceinline__ int dil2orig(int d, int p) {
    return ((p >> 8) << 9) + (d << 8) + (p & 255);
}

__device__ __forceinline__ uint32_t smem_to_u32(const void* smem_ptr) {
    uint32_t addr;
    asm("{ .reg .u64 tmp; cvta.to.shared.u64 tmp, %1; cvt.u32.u64 %0, tmp; }"
        : "=r"(addr) : "l"(smem_ptr));
    return addr;
}

// ===========================================================================
// family-generic tensor-core primitives
// ===========================================================================
__device__ __forceinline__ void ldsm4(uint32_t* r, uint32_t addr) {
    asm volatile("ldmatrix.sync.aligned.m8n8.x4.shared.b16 {%0,%1,%2,%3}, [%4];\n"
                 : "=r"(r[0]), "=r"(r[1]), "=r"(r[2]), "=r"(r[3]) : "r"(addr));
}
__device__ __forceinline__ void ldsm4t(uint32_t* r, uint32_t addr) {
    asm volatile("ldmatrix.sync.aligned.m8n8.x4.trans.shared.b16 {%0,%1,%2,%3}, [%4];\n"
                 : "=r"(r[0]), "=r"(r[1]), "=r"(r[2]), "=r"(r[3]) : "r"(addr));
}
// fp16 mma (fp32 accumulate)
__device__ __forceinline__ void mma16816h(float* c, const uint32_t* a,
                                          uint32_t b0, uint32_t b1) {
    asm volatile(
        "mma.sync.aligned.m16n8k16.row.col.f32.f16.f16.f32 "
        "{%0,%1,%2,%3}, {%4,%5,%6,%7}, {%8,%9}, {%0,%1,%2,%3};\n"
        : "+f"(c[0]), "+f"(c[1]), "+f"(c[2]), "+f"(c[3])
        : "r"(a[0]), "r"(a[1]), "r"(a[2]), "r"(a[3]), "r"(b0), "r"(b1));
}
__device__ __forceinline__ void cp_async16(uint32_t saddr, const void* gptr) {
    asm volatile("cp.async.cg.shared.global [%0], [%1], 16;\n"
                 :: "r"(saddr), "l"(gptr));
}
__device__ __forceinline__ void cp_async16z(uint32_t saddr, const void* gptr, int srcbytes) {
    asm volatile("cp.async.cg.shared.global [%0], [%1], 16, %2;\n"
                 :: "r"(saddr), "l"(gptr), "r"(srcbytes));
}
#define CP_COMMIT() asm volatile("cp.async.commit_group;\n" ::: "memory")
#define CP_WAIT0()  asm volatile("cp.async.wait_group 0;\n" ::: "memory")
#define CP_WAIT1()  asm volatile("cp.async.wait_group 1;\n" ::: "memory")

// gemm smem tile layout: 128 rows x 32 elem (4 x 16B chunks/row)
__device__ __forceinline__ uint32_t sw_off(int r, int c) {
    return (uint32_t)(((r >> 1) << 7) + ((r & 1) << 6) +
                      (((c ^ ((r >> 1) & 3)) & 3) << 4));
}
// attn smem tile layout: rows x 64 elem (8 x 16B chunks/row), xor swizzle
__device__ __forceinline__ uint32_t att_off(int r, int ch) {
    return (uint32_t)((r << 7) + (((ch ^ (r & 7)) & 7) << 4));
}

__device__ __forceinline__ uint32_t pack_f16x2(float a, float b) {
    __half2 t = __floats2half2_rn(a, b);
    return *(uint32_t*)&t;
}

// ===========================================================================
// split helpers
// ===========================================================================
__device__ __forceinline__ void hsplit(float f, __half& h, __half& l) {
    h = __float2half(f);
    l = __float2half(f - __half2float(h));
}

struct __align__(8) H4 { __half v[4]; };

// elementwise fp16 split: x -> hi/lo
__global__ __launch_bounds__(256) void split_kernel(
    const float* __restrict__ src, __half* __restrict__ hi,
    __half* __restrict__ lo) {
    const int idx = blockIdx.x * 256 + threadIdx.x;
    float4 v = ((const float4*)src)[idx];
    H4 h, l;
    hsplit(v.x, h.v[0], l.v[0]);
    hsplit(v.y, h.v[1], l.v[1]);
    hsplit(v.z, h.v[2], l.v[2]);
    hsplit(v.w, h.v[3], l.v[3]);
    ((H4*)hi)[idx] = h;
    ((H4*)lo)[idx] = l;
}

// transpose + fp16 convert all 4 weights; blockIdx.z selects.
__global__ __launch_bounds__(256) void wsplit_all_kernel(
    const float* __restrict__ wq, const float* __restrict__ wk,
    const float* __restrict__ wv, const float* __restrict__ wo) {
    const int z = blockIdx.z;
    const float* w = (z == 0) ? wq : (z == 1) ? wk : (z == 2) ? wv : wo;
    __half* wT = (z == 0) ? g_wqT : (z == 1) ? g_wkT : (z == 2) ? g_wvT : g_woT;

    __shared__ float t[32][33];
    const int bx = blockIdx.x << 5;
    const int by = blockIdx.y << 5;
    const int tx = threadIdx.x & 31, ty = threadIdx.x >> 5;
#pragma unroll
    for (int i = 0; i < 32; i += 8)
        t[ty + i][tx] = w[(size_t)(by + ty + i) * DIMV + bx + tx];
    __syncthreads();
#pragma unroll
    for (int i = 0; i < 32; i += 8)
        wT[(size_t)(bx + ty + i) * DIMV + by + tx] = __float2half(t[tx][ty + i]);
}

// ===========================================================================
// fp16 GEMM: C = (Ah [+ Al]) @ BhT + bias  (Alo == nullptr -> 1-pass)
// CTA 128x128, K-stage 32, 3-stage cp.async ring (3 x 24KB smem).
// ===========================================================================
#define STAGE_BYTES 24576
#define GEMM_SMEM_REQ (3 * STAGE_BYTES)

__device__ __forceinline__ void load_stage(
    uint32_t sbase, const __half* __restrict__ Ahi,
    const __half* __restrict__ Alo, const __half* __restrict__ B,
    int bm, int bn, int k0, int tid) {
#pragma unroll
    for (int j = 0; j < 6; j++) {
        const int chunk = tid + (j << 8);
        const int tile = chunk >> 9;          // 0..2
        const int idx = chunk & 511;
        const int r = idx >> 2, c = idx & 3;
        const uint32_t saddr = sbase + (uint32_t)(tile << 13) + sw_off(r, c);
        const __half* gp;
        if (tile == 0)      gp = Ahi + (size_t)(bm + r) * DIMV + k0 + c * 8;
        else if (tile == 1) {
            if (!Alo) continue;
            gp = Alo + (size_t)(bm + r) * DIMV + k0 + c * 8;
        }
        else                gp = B + (size_t)(bn + r) * DIMV + k0 + c * 8;
        cp_async16(saddr, gp);
    }
}

__device__ __forceinline__ void gemm_core(
    const __half* __restrict__ Ahi, const __half* __restrict__ Alo,
    const __half* __restrict__ B,
    const float* __restrict__ bias, float* __restrict__ C,
    __half* __restrict__ Chi,
    uint32_t sb, int bm, int bn) {
    const int tid = threadIdx.x;
    const int wid = tid >> 5, lane = tid & 31;
    const int wm = (wid & 1) << 6;
    const int wn = (wid >> 1) << 5;
    const int lr = lane & 15;
    const int lhalf = lane >> 4;

    float acc[4][4][4];
#pragma unroll
    for (int i = 0; i < 4; i++)
#pragma unroll
        for (int j = 0; j < 4; j++)
#pragma unroll
            for (int k = 0; k < 4; k++) acc[i][j][k] = 0.f;

    load_stage(sb, Ahi, Alo, B, bm, bn, 0, tid);
    CP_COMMIT();
    load_stage(sb + STAGE_BYTES, Ahi, Alo, B, bm, bn, 32, tid);
    CP_COMMIT();

    int bufsel = 0;
    for (int s = 0; s < 32; s++) {
        if (s == 31) { CP_WAIT0(); } else { CP_WAIT1(); }
        __syncthreads();
        if (s + 2 < 32) {
            int nb = bufsel + 2;
            if (nb >= 3) nb -= 3;
            load_stage(sb + (uint32_t)nb * STAGE_BYTES, Ahi, Alo, B,
                       bm, bn, (s + 2) << 5, tid);
            CP_COMMIT();
        }

        const uint32_t buf = sb + (uint32_t)bufsel * STAGE_BYTES;
        bufsel = (bufsel == 2) ? 0 : bufsel + 1;
#pragma unroll
        for (int kk = 0; kk < 2; kk++) {
            const int cb = (kk << 1) + lhalf;
            uint32_t a[4][4], bh[2][4];
#pragma unroll
            for (int mi = 0; mi < 4; mi++)
                ldsm4(a[mi], buf + sw_off(wm + (mi << 4) + lr, cb));
#pragma unroll
            for (int np = 0; np < 2; np++)
                ldsm4(bh[np], buf + 16384 + sw_off(wn + (np << 4) + lr, cb));
            // pass 1: Ah x B
#pragma unroll
            for (int mi = 0; mi < 4; mi++) {
                mma16816h(acc[mi][0], a[mi], bh[0][0], bh[0][2]);
                mma16816h(acc[mi][1], a[mi], bh[0][1], bh[0][3]);
                mma16816h(acc[mi][2], a[mi], bh[1][0], bh[1][2]);
                mma16816h(acc[mi][3], a[mi], bh[1][1], bh[1][3]);
            }
            // pass 2: Al x B (skipped when Alo == nullptr)
            if (Alo) {
#pragma unroll
                for (int mi = 0; mi < 4; mi++)
                    ldsm4(a[mi], buf + 8192 + sw_off(wm + (mi << 4) + lr, cb));
#pragma unroll
                for (int mi = 0; mi < 4; mi++) {
                    mma16816h(acc[mi][0], a[mi], bh[0][0], bh[0][2]);
                    mma16816h(acc[mi][1], a[mi], bh[0][1], bh[0][3]);
                    mma16816h(acc[mi][2], a[mi], bh[1][0], bh[1][2]);
                    mma16816h(acc[mi][3], a[mi], bh[1][1], bh[1][3]);
                }
            }
        }
        // no bottom sync: next iteration's wait+sync protects stage reuse
    }

    const int crow = lane >> 2;
    const int ccol = (lane & 3) << 1;
#pragma unroll
    for (int ni = 0; ni < 4; ni++) {
        const int col = bn + wn + (ni << 3) + ccol;
        const float2 bv = *(const float2*)&bias[col];
#pragma unroll
        for (int mi = 0; mi < 4; mi++) {
            const int row = bm + wm + (mi << 4) + crow;
            const float v00 = acc[mi][ni][0] + bv.x, v01 = acc[mi][ni][1] + bv.y;
            const float v10 = acc[mi][ni][2] + bv.x, v11 = acc[mi][ni][3] + bv.y;
            if (Chi) {
                *(uint32_t*)&Chi[(size_t)row * DIMV + col] = pack_f16x2(v00, v01);
                *(uint32_t*)&Chi[(size_t)(row + 8) * DIMV + col] = pack_f16x2(v10, v11);
            } else {
                *(float2*)&C[(size_t)row * DIMV + col] = make_float2(v00, v01);
                *(float2*)&C[(size_t)(row + 8) * DIMV + col] = make_float2(v10, v11);
            }
        }
    }
}

// fused Q/K/V projection: grid (8, 68, 3). V emitted as single fp16.
__global__ __launch_bounds__(256, 2)
void gemm_qkv_kernel(const __half* __restrict__ Ahi,
                     const __half* __restrict__ Alo,
                     const float* __restrict__ bq,
                     const float* __restrict__ bk,
                     const float* __restrict__ bv) {
    extern __shared__ char smem[];
    const uint32_t sb = smem_to_u32(smem);
    const int z = blockIdx.z;
    const __half* B = (z == 0) ? g_wqT : (z == 1) ? g_wkT : g_wvT;
    const float* bias = (z == 0) ? bq : (z == 1) ? bk : bv;
    float* C = (z == 0) ? g_q : (z == 1) ? g_k : nullptr;
    __half* Chi = (z == 2) ? g_vh : nullptr;
    gemm_core(Ahi, Alo, B, bias, C, Chi, sb,
              blockIdx.y << 7, blockIdx.x << 7);
}

// output projection: A is single fp16 (attention output) -> 1-pass
__global__ __launch_bounds__(256, 2)
void gemm_out_kernel(const __half* __restrict__ Ahi,
                     const float* __restrict__ bias,
                     float* __restrict__ C) {
    extern __shared__ char smem[];
    const uint32_t sb = smem_to_u32(smem);
    gemm_core(Ahi, nullptr, g_woT, bias, C, nullptr, sb,
              blockIdx.y << 7, blockIdx.x << 7);
}

// ---------------------------------------------------------------------------
// Fused RMSNorm + RoPE + single-fp16 emit. blockIdx.y: 0 = Q (scaled), 1 = K.
// ---------------------------------------------------------------------------
__global__ __launch_bounds__(256) void normrope_split_kernel(
    const float* __restrict__ srcq, const float* __restrict__ srck,
    const float* __restrict__ gq, const float* __restrict__ gk,
    const float* __restrict__ cs, const float* __restrict__ sn,
    __half* __restrict__ qh, __half* __restrict__ kh) {
    const int s = blockIdx.x;
    const int isq = (blockIdx.y == 0);
    const float* src = isq ? srcq : srck;
    const float* g = isq ? gq : gk;
    __half* dst = isq ? qh : kh;
    const float scale = isq ? 0.125f : 1.0f;
    const int tid = threadIdx.x;

    float4 v = *(const float4*)&src[(size_t)s * DIMV + (tid << 2)];
    float ss = v.x * v.x + v.y * v.y + v.z * v.z + v.w * v.w;
#pragma unroll
    for (int o = 16; o; o >>= 1) ss += __shfl_xor_sync(0xffffffffu, ss, o);

    __shared__ float red[8];
    __shared__ float rtot;
    if ((tid & 31) == 0) red[tid >> 5] = ss;
    __syncthreads();
    if (tid == 0) {
        float t = 0.f;
#pragma unroll
        for (int i = 0; i < 8; i++) t += red[i];
        rtot = rsqrtf(t * (1.0f / 1024.0f) + 1e-6f);
    }
    __syncthreads();
    const float r = rtot;

    float4 gv = *(const float4*)&g[tid << 2];
    const float a0 = v.x * r * gv.x, b0 = v.y * r * gv.y;
    const float a1 = v.z * r * gv.z, b1 = v.w * r * gv.w;

    const int p0 = tid << 1;
    const int r0 = p0 & 31, r1 = (p0 + 1) & 31;
    const float c0 = cs[s * 32 + r0], s0 = sn[s * 32 + r0];
    const float c1 = cs[s * 32 + r1], s1 = sn[s * 32 + r1];

    float o0 = (a0 * c0 - b0 * s0) * scale;
    float o1 = (a0 * s0 + b0 * c0) * scale;
    float o2 = (a1 * c1 - b1 * s1) * scale;
    float o3 = (a1 * s1 + b1 * c1) * scale;

    const size_t base = (size_t)s * DIMV + (tid << 2);
    *(uint32_t*)&dst[base] = pack_f16x2(o0, o1);
    *(uint32_t*)&dst[base + 2] = pack_f16x2(o2, o3);
}

// ===========================================================================
// Tensor-core flash attention. QK: fp16 1-pass; PV: fp16 1-pass.
// 3-stage cp.async ring: stage = K 8KB + V 8KB = 16KB; 3 stages = 48KB.
// ===========================================================================
#define ATT_STAGE 16384
#define ATT_SMEM  (3 * ATT_STAGE)

__global__ __launch_bounds__(128)
void attn_tc_kernel(const __half* __restrict__ qh_g,
                    const __half* __restrict__ kh, const __half* __restrict__ vh,
                    __half* __restrict__ oh) {
    extern __shared__ char smem[];
    const uint32_t sb = smem_to_u32(smem);
    const int d = blockIdx.z, h = blockIdx.y;
    const int q0 = blockIdx.x << 6;
    const int tid = threadIdx.x;
    const int warp = tid >> 5, lane = tid & 31;
    const int wq = warp << 4;
    const int lr = lane & 15, lhf = lane >> 4;
    const int qr = lane >> 2, qc = (lane & 3) << 1;

    // prologue: borrow stage-0 smem for Q (8KB)
#pragma unroll
    for (int t = 0; t < 4; t++) {
        const int idx = tid + (t << 7);
        const int r = idx >> 3, ch = idx & 7;
        const int tok = dil2orig(d, q0 + r);
        const size_t go = (size_t)tok * DIMV + h * HD + (ch << 3);
        *(uint4*)(smem + att_off(r, ch)) = *(const uint4*)&qh_g[go];
    }
    __syncthreads();

    uint32_t qf[4][4];
#pragma unroll
    for (int s = 0; s < 4; s++)
        ldsm4(qf[s], sb + att_off(wq + lr, (s << 1) + lhf));
    __syncthreads();

    float m0 = -1e30f, m1 = -1e30f, l0 = 0.f, l1 = 0.f;
    float o[8][4];
#pragma unroll
    for (int j = 0; j < 8; j++)
#pragma unroll
        for (int k = 0; k < 4; k++) o[j][k] = 0.f;

    const int kt_lo = (q0 >= WIN) ? (q0 - WIN) : 0;
    const int kt_hi = min(SD, q0 + BQ + WIN);
    const int nt = (kt_hi - kt_lo + BK - 1) / BK;
    const int row0 = q0 + wq + qr, row1 = row0 + 8;

    auto stage_load = [&](int st, int kt) {
        const uint32_t stg = sb + (uint32_t)st * ATT_STAGE;
#pragma unroll
        for (int t = 0; t < 8; t++) {
            const int cid = tid + (t << 7);
            const int buf = cid >> 9;          // 0..1
            const int idx = cid & 511;
            const int r = idx >> 3, ch = idx & 7;
            const int pk = kt + r;
            const int ok = pk < SREAL;
            const int tok = ok ? dil2orig(d, pk) : 0;
            const size_t go = ((size_t)tok * DIMV + h * HD + (ch << 3)) * 2;
            const char* src = (buf == 0) ? (const char*)kh : (const char*)vh;
            cp_async16z(stg + (buf << 13) + att_off(r, ch), src + go, ok ? 16 : 0);
        }
    };

    stage_load(0, kt_lo);
    CP_COMMIT();
    if (nt > 1) { stage_load(1, kt_lo + BK); CP_COMMIT(); }

    int bufsel = 0;
    for (int i = 0; i < nt; i++) {
        const int kt = kt_lo + i * BK;
        if (i >= nt - 2) { CP_WAIT0(); } else { CP_WAIT1(); }
        __syncthreads();
        if (i + 2 < nt) {
            int nb = bufsel + 2;
            if (nb >= 3) nb -= 3;
            stage_load(nb, kt + 2 * BK);
            CP_COMMIT();
        }

        const uint32_t sK = sb + (uint32_t)bufsel * ATT_STAGE;
        const uint32_t sV = sK + 8192;
        bufsel = (bufsel == 2) ? 0 : bufsel + 1;

        // --- scores: fp16 1-pass ---
        float c[8][4];
#pragma unroll
        for (int j = 0; j < 8; j++)
#pragma unroll
            for (int k = 0; k < 4; k++) c[j][k] = 0.f;

#pragma unroll
        for (int s = 0; s < 4; s++) {
#pragma unroll
            for (int g = 0; g < 4; g++) {
                uint32_t bh[4];
                ldsm4(bh, sK + att_off((g << 4) + lr, (s << 1) + lhf));
                mma16816h(c[2 * g],     qf[s], bh[0], bh[2]);
                mma16816h(c[2 * g + 1], qf[s], bh[1], bh[3]);
            }
        }

        const bool edge = (kt < q0 - WIN + BK) || (kt >= q0 + WIN);
        if (edge) {
#pragma unroll
            for (int j = 0; j < 8; j++) {
                const int pk = kt + (j << 3) + qc;
                if (abs(row0 - pk) > WIN)       c[j][0] = -1e9f;
                if (abs(row0 - pk - 1) > WIN)   c[j][1] = -1e9f;
                if (abs(row1 - pk) > WIN)       c[j][2] = -1e9f;
                if (abs(row1 - pk - 1) > WIN)   c[j][3] = -1e9f;
            }
        }

        // --- online softmax ---
        float tm0 = -1e30f, tm1 = -1e30f;
#pragma unroll
        for (int j = 0; j < 8; j++) {
            tm0 = fmaxf(tm0, fmaxf(c[j][0], c[j][1]));
            tm1 = fmaxf(tm1, fmaxf(c[j][2], c[j][3]));
        }
        tm0 = fmaxf(tm0, __shfl_xor_sync(0xffffffffu, tm0, 1));
        tm0 = fmaxf(tm0, __shfl_xor_sync(0xffffffffu, tm0, 2));
        tm1 = fmaxf(tm1, __shfl_xor_sync(0xffffffffu, tm1, 1));
        tm1 = fmaxf(tm1, __shfl_xor_sync(0xffffffffu, tm1, 2));

        const float mn0 = fmaxf(m0, tm0), mn1 = fmaxf(m1, tm1);
        const float cor0 = __expf(m0 - mn0), cor1 = __expf(m1 - mn1);
        m0 = mn0; m1 = mn1;

        float s0 = 0.f, s1 = 0.f;
#pragma unroll
        for (int j = 0; j < 8; j++) {
            c[j][0] = __expf(c[j][0] - mn0);
            c[j][1] = __expf(c[j][1] - mn0);
            c[j][2] = __expf(c[j][2] - mn1);
            c[j][3] = __expf(c[j][3] - mn1);
            s0 += c[j][0] + c[j][1];
            s1 += c[j][2] + c[j][3];
        }
        s0 += __shfl_xor_sync(0xffffffffu, s0, 1);
        s0 += __shfl_xor_sync(0xffffffffu, s0, 2);
        s1 += __shfl_xor_sync(0xffffffffu, s1, 1);
        s1 += __shfl_xor_sync(0xffffffffu, s1, 2);
        l0 = l0 * cor0 + s0;
        l1 = l1 * cor1 + s1;
#pragma unroll
        for (int j = 0; j < 8; j++) {
            o[j][0] *= cor0; o[j][1] *= cor0;
            o[j][2] *= cor1; o[j][3] *= cor1;
        }

        // --- PV: fp16 1-pass, P packed directly ---
#pragma unroll
        for (int s = 0; s < 4; s++) {
            uint32_t ap[4];
            ap[0] = pack_f16x2(c[2 * s][0],     c[2 * s][1]);
            ap[1] = pack_f16x2(c[2 * s][2],     c[2 * s][3]);
            ap[2] = pack_f16x2(c[2 * s + 1][0], c[2 * s + 1][1]);
            ap[3] = pack_f16x2(c[2 * s + 1][2], c[2 * s + 1][3]);
#pragma unroll
            for (int g = 0; g < 4; g++) {
                uint32_t bh[4];
                ldsm4t(bh, sV + att_off((s << 4) + lr, (g << 1) + lhf));
                mma16816h(o[2 * g],     ap, bh[0], bh[1]);
                mma16816h(o[2 * g + 1], ap, bh[2], bh[3]);
            }
        }
    }

    // epilogue: normalize, store single fp16 (feeds 1-pass out-GEMM)
    const float inv0 = 1.0f / l0, inv1 = 1.0f / l1;
    const int tok0 = dil2orig(d, row0);
    const int tok1 = dil2orig(d, row1);
#pragma unroll
    for (int j = 0; j < 8; j++) {
        const int col = h * HD + (j << 3) + qc;
        *(uint32_t*)&oh[(size_t)tok0 * DIMV + col] =
            pack_f16x2(o[j][0] * inv0, o[j][1] * inv0);
        *(uint32_t*)&oh[(size_t)tok1 * DIMV + col] =
            pack_f16x2(o[j][2] * inv1, o[j][3] * inv1);
    }
}

// ---------------------------------------------------------------------------
extern "C" void kernel_launch(void* const* d_in, const int* in_sizes, int n_in,
                              void* d_out, int out_size) {
    (void)in_sizes; (void)n_in; (void)out_size;
    const float* x  = (const float*)d_in[0];
    const float* fc = (const float*)d_in[1];
    const float* fs = (const float*)d_in[2];
    const float* wq = (const float*)d_in[3];
    const float* bq = (const float*)d_in[4];
    const float* wk = (const float*)d_in[5];
    const float* bk = (const float*)d_in[6];
    const float* wv = (const float*)d_in[7];
    const float* bv = (const float*)d_in[8];
    const float* wo = (const float*)d_in[9];
    const float* bo = (const float*)d_in[10];
    const float* gq = (const float*)d_in[11];
    const float* gk = (const float*)d_in[12];
    float* out = (float*)d_out;

    float *qb, *kb;
    cudaGetSymbolAddress((void**)&qb, g_q);
    cudaGetSymbolAddress((void**)&kb, g_k);
    __half *ahi, *alo, *vh, *qh, *kh;
    cudaGetSymbolAddress((void**)&ahi, g_ahi);
    cudaGetSymbolAddress((void**)&alo, g_alo);
    cudaGetSymbolAddress((void**)&vh, g_vh);
    cudaGetSymbolAddress((void**)&qh, g_qh);
    cudaGetSymbolAddress((void**)&kh, g_kh);

    cudaFuncSetAttribute(gemm_qkv_kernel,
                         cudaFuncAttributeMaxDynamicSharedMemorySize, GEMM_SMEM_REQ);
    cudaFuncSetAttribute(gemm_out_kernel,
                         cudaFuncAttributeMaxDynamicSharedMemorySize, GEMM_SMEM_REQ);
    cudaFuncSetAttribute(attn_tc_kernel,
                         cudaFuncAttributeMaxDynamicSharedMemorySize, ATT_SMEM);

    wsplit_all_kernel<<<dim3(32, 32, 4), 256>>>(wq, wk, wv, wo);
    split_kernel<<<(S_LEN * DIMV) / 1024, 256>>>(x, ahi, alo);
    gemm_qkv_kernel<<<dim3(DIMV / 128, S_LEN / 128, 3), 256, GEMM_SMEM_REQ>>>(
        ahi, alo, bq, bk, bv);
    normrope_split_kernel<<<dim3(S_LEN, 2), 256>>>(qb, kb, gq, gk, fc, fs,
                                                   qh, kh);
    attn_tc_kernel<<<dim3(SREAL / BQ, NH, 2), 128, ATT_SMEM>>>(
        qh, kh, vh, ahi);
    gemm_out_kernel<<<dim3(DIMV / 128, S_LEN / 128), 256, GEMM_SMEM_REQ>>>(
        ahi, bo, out);
}

// round 17
// speedup vs baseline: 1.4749x; 1.3467x over previous
#include <cuda_runtime.h>
#include <cuda_bf16.h>
#include <cuda_fp16.h>
#include <math.h>
#include <stdint.h>

#define S_LEN 8704
#define DIMV  1024
#define NH    16
#define HD    64
#define SD    4608
#define SREAL 4352
#define WIN   512
#define BQ    64
#define BK    64

// fp32 activation buffers
__device__ float g_q[S_LEN * DIMV];
__device__ float g_k[S_LEN * DIMV];

// fp16 activations (x for QKV GEMM; reused for attn output)
__device__ __half g_ah[S_LEN * DIMV];

// fp16 attention operands: Q, K, V all single fp16
__device__ __half g_qh[S_LEN * DIMV];
__device__ __half g_kh[S_LEN * DIMV];
__device__ __half g_vh[S_LEN * DIMV];

// fp16 transposed weights [N][K]
__device__ __half g_wqT[DIMV * DIMV];
__device__ __half g_wkT[DIMV * DIMV];
__device__ __half g_wvT[DIMV * DIMV];
__device__ __half g_woT[DIMV * DIMV];

__device__ __forceinline__ int dil2orig(int d, int p) {
    return ((p >> 8) << 9) + (d << 8) + (p & 255);
}

__device__ __forceinline__ uint32_t smem_to_u32(const void* smem_ptr) {
    uint32_t addr;
    asm("{ .reg .u64 tmp; cvta.to.shared.u64 tmp, %1; cvt.u32.u64 %0, tmp; }"
        : "=r"(addr) : "l"(smem_ptr));
    return addr;
}

// ===========================================================================
// family-generic tensor-core primitives
// ===========================================================================
__device__ __forceinline__ void ldsm4(uint32_t* r, uint32_t addr) {
    asm volatile("ldmatrix.sync.aligned.m8n8.x4.shared.b16 {%0,%1,%2,%3}, [%4];\n"
                 : "=r"(r[0]), "=r"(r[1]), "=r"(r[2]), "=r"(r[3]) : "r"(addr));
}
__device__ __forceinline__ void ldsm4t(uint32_t* r, uint32_t addr) {
    asm volatile("ldmatrix.sync.aligned.m8n8.x4.trans.shared.b16 {%0,%1,%2,%3}, [%4];\n"
                 : "=r"(r[0]), "=r"(r[1]), "=r"(r[2]), "=r"(r[3]) : "r"(addr));
}
// fp16 mma (fp32 accumulate)
__device__ __forceinline__ void mma16816h(float* c, const uint32_t* a,
                                          uint32_t b0, uint32_t b1) {
    asm volatile(
        "mma.sync.aligned.m16n8k16.row.col.f32.f16.f16.f32 "
        "{%0,%1,%2,%3}, {%4,%5,%6,%7}, {%8,%9}, {%0,%1,%2,%3};\n"
        : "+f"(c[0]), "+f"(c[1]), "+f"(c[2]), "+f"(c[3])
        : "r"(a[0]), "r"(a[1]), "r"(a[2]), "r"(a[3]), "r"(b0), "r"(b1));
}
__device__ __forceinline__ void cp_async16(uint32_t saddr, const void* gptr) {
    asm volatile("cp.async.cg.shared.global [%0], [%1], 16;\n"
                 :: "r"(saddr), "l"(gptr));
}
__device__ __forceinline__ void cp_async16z(uint32_t saddr, const void* gptr, int srcbytes) {
    asm volatile("cp.async.cg.shared.global [%0], [%1], 16, %2;\n"
                 :: "r"(saddr), "l"(gptr), "r"(srcbytes));
}
#define CP_COMMIT() asm volatile("cp.async.commit_group;\n" ::: "memory")
#define CP_WAIT0()  asm volatile("cp.async.wait_group 0;\n" ::: "memory")
#define CP_WAIT1()  asm volatile("cp.async.wait_group 1;\n" ::: "memory")

// gemm smem tile layout: 128 rows x 32 elem (4 x 16B chunks/row)
__device__ __forceinline__ uint32_t sw_off(int r, int c) {
    return (uint32_t)(((r >> 1) << 7) + ((r & 1) << 6) +
                      (((c ^ ((r >> 1) & 3)) & 3) << 4));
}
// attn smem tile layout: rows x 64 elem (8 x 16B chunks/row), xor swizzle
__device__ __forceinline__ uint32_t att_off(int r, int ch) {
    return (uint32_t)((r << 7) + (((ch ^ (r & 7)) & 7) << 4));
}

__device__ __forceinline__ uint32_t pack_f16x2(float a, float b) {
    __half2 t = __floats2half2_rn(a, b);
    return *(uint32_t*)&t;
}

struct __align__(8) H4 { __half v[4]; };

// elementwise fp16 convert: x -> fp16
__global__ __launch_bounds__(256) void convert_kernel(
    const float* __restrict__ src, __half* __restrict__ dst) {
    const int idx = blockIdx.x * 256 + threadIdx.x;
    float4 v = ((const float4*)src)[idx];
    H4 h;
    h.v[0] = __float2half(v.x);
    h.v[1] = __float2half(v.y);
    h.v[2] = __float2half(v.z);
    h.v[3] = __float2half(v.w);
    ((H4*)dst)[idx] = h;
}

// transpose + fp16 convert all 4 weights; blockIdx.z selects.
__global__ __launch_bounds__(256) void wsplit_all_kernel(
    const float* __restrict__ wq, const float* __restrict__ wk,
    const float* __restrict__ wv, const float* __restrict__ wo) {
    const int z = blockIdx.z;
    const float* w = (z == 0) ? wq : (z == 1) ? wk : (z == 2) ? wv : wo;
    __half* wT = (z == 0) ? g_wqT : (z == 1) ? g_wkT : (z == 2) ? g_wvT : g_woT;

    __shared__ float t[32][33];
    const int bx = blockIdx.x << 5;
    const int by = blockIdx.y << 5;
    const int tx = threadIdx.x & 31, ty = threadIdx.x >> 5;
#pragma unroll
    for (int i = 0; i < 32; i += 8)
        t[ty + i][tx] = w[(size_t)(by + ty + i) * DIMV + bx + tx];
    __syncthreads();
#pragma unroll
    for (int i = 0; i < 32; i += 8)
        wT[(size_t)(bx + ty + i) * DIMV + by + tx] = __float2half(t[tx][ty + i]);
}

// ===========================================================================
// fp16 1-pass GEMM: C = Ah @ BhT + bias
// CTA 128x128, K-stage 32, 3-stage cp.async ring (stage = A 8K + B 8K = 16KB).
// ===========================================================================
#define STAGE_BYTES 16384
#define GEMM_SMEM_REQ (3 * STAGE_BYTES)

__device__ __forceinline__ void load_stage(
    uint32_t sbase, const __half* __restrict__ A, const __half* __restrict__ B,
    int bm, int bn, int k0, int tid) {
#pragma unroll
    for (int j = 0; j < 4; j++) {
        const int chunk = tid + (j << 8);
        const int tile = chunk >> 9;          // 0..1
        const int idx = chunk & 511;
        const int r = idx >> 2, c = idx & 3;
        const uint32_t saddr = sbase + (uint32_t)(tile << 13) + sw_off(r, c);
        const __half* gp = (tile == 0)
            ? A + (size_t)(bm + r) * DIMV + k0 + c * 8
            : B + (size_t)(bn + r) * DIMV + k0 + c * 8;
        cp_async16(saddr, gp);
    }
}

__device__ __forceinline__ void gemm_core(
    const __half* __restrict__ A, const __half* __restrict__ B,
    const float* __restrict__ bias, float* __restrict__ C,
    __half* __restrict__ Chi,
    uint32_t sb, int bm, int bn) {
    const int tid = threadIdx.x;
    const int wid = tid >> 5, lane = tid & 31;
    const int wm = (wid & 1) << 6;
    const int wn = (wid >> 1) << 5;
    const int lr = lane & 15;
    const int lhalf = lane >> 4;

    float acc[4][4][4];
#pragma unroll
    for (int i = 0; i < 4; i++)
#pragma unroll
        for (int j = 0; j < 4; j++)
#pragma unroll
            for (int k = 0; k < 4; k++) acc[i][j][k] = 0.f;

    load_stage(sb, A, B, bm, bn, 0, tid);
    CP_COMMIT();
    load_stage(sb + STAGE_BYTES, A, B, bm, bn, 32, tid);
    CP_COMMIT();

    int bufsel = 0;
    for (int s = 0; s < 32; s++) {
        if (s == 31) { CP_WAIT0(); } else { CP_WAIT1(); }
        __syncthreads();
        if (s + 2 < 32) {
            int nb = bufsel + 2;
            if (nb >= 3) nb -= 3;
            load_stage(sb + (uint32_t)nb * STAGE_BYTES, A, B,
                       bm, bn, (s + 2) << 5, tid);
            CP_COMMIT();
        }

        const uint32_t buf = sb + (uint32_t)bufsel * STAGE_BYTES;
        bufsel = (bufsel == 2) ? 0 : bufsel + 1;
#pragma unroll
        for (int kk = 0; kk < 2; kk++) {
            const int cb = (kk << 1) + lhalf;
            uint32_t a[4][4], bh[2][4];
#pragma unroll
            for (int mi = 0; mi < 4; mi++)
                ldsm4(a[mi], buf + sw_off(wm + (mi << 4) + lr, cb));
#pragma unroll
            for (int np = 0; np < 2; np++)
                ldsm4(bh[np], buf + 8192 + sw_off(wn + (np << 4) + lr, cb));
#pragma unroll
            for (int mi = 0; mi < 4; mi++) {
                mma16816h(acc[mi][0], a[mi], bh[0][0], bh[0][2]);
                mma16816h(acc[mi][1], a[mi], bh[0][1], bh[0][3]);
                mma16816h(acc[mi][2], a[mi], bh[1][0], bh[1][2]);
                mma16816h(acc[mi][3], a[mi], bh[1][1], bh[1][3]);
            }
        }
        // no bottom sync: next iteration's wait+sync protects stage reuse
    }

    const int crow = lane >> 2;
    const int ccol = (lane & 3) << 1;
#pragma unroll
    for (int ni = 0; ni < 4; ni++) {
        const int col = bn + wn + (ni << 3) + ccol;
        const float2 bv = *(const float2*)&bias[col];
#pragma unroll
        for (int mi = 0; mi < 4; mi++) {
            const int row = bm + wm + (mi << 4) + crow;
            const float v00 = acc[mi][ni][0] + bv.x, v01 = acc[mi][ni][1] + bv.y;
            const float v10 = acc[mi][ni][2] + bv.x, v11 = acc[mi][ni][3] + bv.y;
            if (Chi) {
                *(uint32_t*)&Chi[(size_t)row * DIMV + col] = pack_f16x2(v00, v01);
                *(uint32_t*)&Chi[(size_t)(row + 8) * DIMV + col] = pack_f16x2(v10, v11);
            } else {
                *(float2*)&C[(size_t)row * DIMV + col] = make_float2(v00, v01);
                *(float2*)&C[(size_t)(row + 8) * DIMV + col] = make_float2(v10, v11);
            }
        }
    }
}

// fused Q/K/V projection: grid (8, 68, 3). V emitted as single fp16.
__global__ __launch_bounds__(256, 2)
void gemm_qkv_kernel(const __half* __restrict__ Ah,
                     const float* __restrict__ bq,
                     const float* __restrict__ bk,
                     const float* __restrict__ bv) {
    extern __shared__ char smem[];
    const uint32_t sb = smem_to_u32(smem);
    const int z = blockIdx.z;
    const __half* B = (z == 0) ? g_wqT : (z == 1) ? g_wkT : g_wvT;
    const float* bias = (z == 0) ? bq : (z == 1) ? bk : bv;
    float* C = (z == 0) ? g_q : (z == 1) ? g_k : nullptr;
    __half* Chi = (z == 2) ? g_vh : nullptr;
    gemm_core(Ah, B, bias, C, Chi, sb, blockIdx.y << 7, blockIdx.x << 7);
}

// output projection: A is single fp16 (attention output)
__global__ __launch_bounds__(256, 2)
void gemm_out_kernel(const __half* __restrict__ Ah,
                     const float* __restrict__ bias,
                     float* __restrict__ C) {
    extern __shared__ char smem[];
    const uint32_t sb = smem_to_u32(smem);
    gemm_core(Ah, g_woT, bias, C, nullptr, sb,
              blockIdx.y << 7, blockIdx.x << 7);
}

// ---------------------------------------------------------------------------
// Fused RMSNorm + RoPE + single-fp16 emit. blockIdx.y: 0 = Q (scaled), 1 = K.
// ---------------------------------------------------------------------------
__global__ __launch_bounds__(256) void normrope_split_kernel(
    const float* __restrict__ srcq, const float* __restrict__ srck,
    const float* __restrict__ gq, const float* __restrict__ gk,
    const float* __restrict__ cs, const float* __restrict__ sn,
    __half* __restrict__ qh, __half* __restrict__ kh) {
    const int s = blockIdx.x;
    const int isq = (blockIdx.y == 0);
    const float* src = isq ? srcq : srck;
    const float* g = isq ? gq : gk;
    __half* dst = isq ? qh : kh;
    const float scale = isq ? 0.125f : 1.0f;
    const int tid = threadIdx.x;

    float4 v = *(const float4*)&src[(size_t)s * DIMV + (tid << 2)];
    float ss = v.x * v.x + v.y * v.y + v.z * v.z + v.w * v.w;
#pragma unroll
    for (int o = 16; o; o >>= 1) ss += __shfl_xor_sync(0xffffffffu, ss, o);

    __shared__ float red[8];
    __shared__ float rtot;
    if ((tid & 31) == 0) red[tid >> 5] = ss;
    __syncthreads();
    if (tid == 0) {
        float t = 0.f;
#pragma unroll
        for (int i = 0; i < 8; i++) t += red[i];
        rtot = rsqrtf(t * (1.0f / 1024.0f) + 1e-6f);
    }
    __syncthreads();
    const float r = rtot;

    float4 gv = *(const float4*)&g[tid << 2];
    const float a0 = v.x * r * gv.x, b0 = v.y * r * gv.y;
    const float a1 = v.z * r * gv.z, b1 = v.w * r * gv.w;

    const int p0 = tid << 1;
    const int r0 = p0 & 31, r1 = (p0 + 1) & 31;
    const float c0 = cs[s * 32 + r0], s0 = sn[s * 32 + r0];
    const float c1 = cs[s * 32 + r1], s1 = sn[s * 32 + r1];

    float o0 = (a0 * c0 - b0 * s0) * scale;
    float o1 = (a0 * s0 + b0 * c0) * scale;
    float o2 = (a1 * c1 - b1 * s1) * scale;
    float o3 = (a1 * s1 + b1 * c1) * scale;

    const size_t base = (size_t)s * DIMV + (tid << 2);
    *(uint32_t*)&dst[base] = pack_f16x2(o0, o1);
    *(uint32_t*)&dst[base + 2] = pack_f16x2(o2, o3);
}

// ===========================================================================
// Tensor-core flash attention. QK: fp16 1-pass; PV: fp16 1-pass.
// 3-stage cp.async ring: stage = K 8KB + V 8KB = 16KB; 3 stages = 48KB.
// ===========================================================================
#define ATT_STAGE 16384
#define ATT_SMEM  (3 * ATT_STAGE)

__global__ __launch_bounds__(128)
void attn_tc_kernel(const __half* __restrict__ qh_g,
                    const __half* __restrict__ kh, const __half* __restrict__ vh,
                    __half* __restrict__ oh) {
    extern __shared__ char smem[];
    const uint32_t sb = smem_to_u32(smem);
    const int d = blockIdx.z, h = blockIdx.y;
    const int q0 = blockIdx.x << 6;
    const int tid = threadIdx.x;
    const int warp = tid >> 5, lane = tid & 31;
    const int wq = warp << 4;
    const int lr = lane & 15, lhf = lane >> 4;
    const int qr = lane >> 2, qc = (lane & 3) << 1;

    // prologue: borrow stage-0 smem for Q (8KB)
#pragma unroll
    for (int t = 0; t < 4; t++) {
        const int idx = tid + (t << 7);
        const int r = idx >> 3, ch = idx & 7;
        const int tok = dil2orig(d, q0 + r);
        const size_t go = (size_t)tok * DIMV + h * HD + (ch << 3);
        *(uint4*)(smem + att_off(r, ch)) = *(const uint4*)&qh_g[go];
    }
    __syncthreads();

    uint32_t qf[4][4];
#pragma unroll
    for (int s = 0; s < 4; s++)
        ldsm4(qf[s], sb + att_off(wq + lr, (s << 1) + lhf));
    __syncthreads();

    float m0 = -1e30f, m1 = -1e30f, l0 = 0.f, l1 = 0.f;
    float o[8][4];
#pragma unroll
    for (int j = 0; j < 8; j++)
#pragma unroll
        for (int k = 0; k < 4; k++) o[j][k] = 0.f;

    const int kt_lo = (q0 >= WIN) ? (q0 - WIN) : 0;
    const int kt_hi = min(SD, q0 + BQ + WIN);
    const int nt = (kt_hi - kt_lo + BK - 1) / BK;
    const int row0 = q0 + wq + qr, row1 = row0 + 8;

    auto stage_load = [&](int st, int kt) {
        const uint32_t stg = sb + (uint32_t)st * ATT_STAGE;
#pragma unroll
        for (int t = 0; t < 8; t++) {
            const int cid = tid + (t << 7);
            const int buf = cid >> 9;          // 0..1
            const int idx = cid & 511;
            const int r = idx >> 3, ch = idx & 7;
            const int pk = kt + r;
            const int ok = pk < SREAL;
            const int tok = ok ? dil2orig(d, pk) : 0;
            const size_t go = ((size_t)tok * DIMV + h * HD + (ch << 3)) * 2;
            const char* src = (buf == 0) ? (const char*)kh : (const char*)vh;
            cp_async16z(stg + (buf << 13) + att_off(r, ch), src + go, ok ? 16 : 0);
        }
    };

    stage_load(0, kt_lo);
    CP_COMMIT();
    if (nt > 1) { stage_load(1, kt_lo + BK); CP_COMMIT(); }

    int bufsel = 0;
    for (int i = 0; i < nt; i++) {
        const int kt = kt_lo + i * BK;
        if (i >= nt - 2) { CP_WAIT0(); } else { CP_WAIT1(); }
        __syncthreads();
        if (i + 2 < nt) {
            int nb = bufsel + 2;
            if (nb >= 3) nb -= 3;
            stage_load(nb, kt + 2 * BK);
            CP_COMMIT();
        }

        const uint32_t sK = sb + (uint32_t)bufsel * ATT_STAGE;
        const uint32_t sV = sK + 8192;
        bufsel = (bufsel == 2) ? 0 : bufsel + 1;

        // --- scores: fp16 1-pass ---
        float c[8][4];
#pragma unroll
        for (int j = 0; j < 8; j++)
#pragma unroll
            for (int k = 0; k < 4; k++) c[j][k] = 0.f;

#pragma unroll
        for (int s = 0; s < 4; s++) {
#pragma unroll
            for (int g = 0; g < 4; g++) {
                uint32_t bh[4];
                ldsm4(bh, sK + att_off((g << 4) + lr, (s << 1) + lhf));
                mma16816h(c[2 * g],     qf[s], bh[0], bh[2]);
                mma16816h(c[2 * g + 1], qf[s], bh[1], bh[3]);
            }
        }

        const bool edge = (kt < q0 - WIN + BK) || (kt >= q0 + WIN);
        if (edge) {
#pragma unroll
            for (int j = 0; j < 8; j++) {
                const int pk = kt + (j << 3) + qc;
                if (abs(row0 - pk) > WIN)       c[j][0] = -1e9f;
                if (abs(row0 - pk - 1) > WIN)   c[j][1] = -1e9f;
                if (abs(row1 - pk) > WIN)       c[j][2] = -1e9f;
                if (abs(row1 - pk - 1) > WIN)   c[j][3] = -1e9f;
            }
        }

        // --- online softmax ---
        float tm0 = -1e30f, tm1 = -1e30f;
#pragma unroll
        for (int j = 0; j < 8; j++) {
            tm0 = fmaxf(tm0, fmaxf(c[j][0], c[j][1]));
            tm1 = fmaxf(tm1, fmaxf(c[j][2], c[j][3]));
        }
        tm0 = fmaxf(tm0, __shfl_xor_sync(0xffffffffu, tm0, 1));
        tm0 = fmaxf(tm0, __shfl_xor_sync(0xffffffffu, tm0, 2));
        tm1 = fmaxf(tm1, __shfl_xor_sync(0xffffffffu, tm1, 1));
        tm1 = fmaxf(tm1, __shfl_xor_sync(0xffffffffu, tm1, 2));

        const float mn0 = fmaxf(m0, tm0), mn1 = fmaxf(m1, tm1);
        const float cor0 = __expf(m0 - mn0), cor1 = __expf(m1 - mn1);
        m0 = mn0; m1 = mn1;

        float s0 = 0.f, s1 = 0.f;
#pragma unroll
        for (int j = 0; j < 8; j++) {
            c[j][0] = __expf(c[j][0] - mn0);
            c[j][1] = __expf(c[j][1] - mn0);
            c[j][2] = __expf(c[j][2] - mn1);
            c[j][3] = __expf(c[j][3] - mn1);
            s0 += c[j][0] + c[j][1];
            s1 += c[j][2] + c[j][3];
        }
        s0 += __shfl_xor_sync(0xffffffffu, s0, 1);
        s0 += __shfl_xor_sync(0xffffffffu, s0, 2);
        s1 += __shfl_xor_sync(0xffffffffu, s1, 1);
        s1 += __shfl_xor_sync(0xffffffffu, s1, 2);
        l0 = l0 * cor0 + s0;
        l1 = l1 * cor1 + s1;
#pragma unroll
        for (int j = 0; j < 8; j++) {
            o[j][0] *= cor0; o[j][1] *= cor0;
            o[j][2] *= cor1; o[j][3] *= cor1;
        }

        // --- PV: fp16 1-pass, P packed directly ---
#pragma unroll
        for (int s = 0; s < 4; s++) {
            uint32_t ap[4];
            ap[0] = pack_f16x2(c[2 * s][0],     c[2 * s][1]);
            ap[1] = pack_f16x2(c[2 * s][2],     c[2 * s][3]);
            ap[2] = pack_f16x2(c[2 * s + 1][0], c[2 * s + 1][1]);
            ap[3] = pack_f16x2(c[2 * s + 1][2], c[2 * s + 1][3]);
#pragma unroll
            for (int g = 0; g < 4; g++) {
                uint32_t bh[4];
                ldsm4t(bh, sV + att_off((s << 4) + lr, (g << 1) + lhf));
                mma16816h(o[2 * g],     ap, bh[0], bh[1]);
                mma16816h(o[2 * g + 1], ap, bh[2], bh[3]);
            }
        }
    }

    // epilogue: normalize, store single fp16 (feeds 1-pass out-GEMM)
    const float inv0 = 1.0f / l0, inv1 = 1.0f / l1;
    const int tok0 = dil2orig(d, row0);
    const int tok1 = dil2orig(d, row1);
#pragma unroll
    for (int j = 0; j < 8; j++) {
        const int col = h * HD + (j << 3) + qc;
        *(uint32_t*)&oh[(size_t)tok0 * DIMV + col] =
            pack_f16x2(o[j][0] * inv0, o[j][1] * inv0);
        *(uint32_t*)&oh[(size_t)tok1 * DIMV + col] =
            pack_f16x2(o[j][2] * inv1, o[j][3] * inv1);
    }
}

// ---------------------------------------------------------------------------
extern "C" void kernel_launch(void* const* d_in, const int* in_sizes, int n_in,
                              void* d_out, int out_size) {
    (void)in_sizes; (void)n_in; (void)out_size;
    const float* x  = (const float*)d_in[0];
    const float* fc = (const float*)d_in[1];
    const float* fs = (const float*)d_in[2];
    const float* wq = (const float*)d_in[3];
    const float* bq = (const float*)d_in[4];
    const float* wk = (const float*)d_in[5];
    const float* bk = (const float*)d_in[6];
    const float* wv = (const float*)d_in[7];
    const float* bv = (const float*)d_in[8];
    const float* wo = (const float*)d_in[9];
    const float* bo = (const float*)d_in[10];
    const float* gq = (const float*)d_in[11];
    const float* gk = (const float*)d_in[12];
    float* out = (float*)d_out;

    float *qb, *kb;
    cudaGetSymbolAddress((void**)&qb, g_q);
    cudaGetSymbolAddress((void**)&kb, g_k);
    __half *ah, *vh, *qh, *kh;
    cudaGetSymbolAddress((void**)&ah, g_ah);
    cudaGetSymbolAddress((void**)&vh, g_vh);
    cudaGetSymbolAddress((void**)&qh, g_qh);
    cudaGetSymbolAddress((void**)&kh, g_kh);

    cudaFuncSetAttribute(gemm_qkv_kernel,
                         cudaFuncAttributeMaxDynamicSharedMemorySize, GEMM_SMEM_REQ);
    cudaFuncSetAttribute(gemm_out_kernel,
                         cudaFuncAttributeMaxDynamicSharedMemorySize, GEMM_SMEM_REQ);
    cudaFuncSetAttribute(attn_tc_kernel,
                         cudaFuncAttributeMaxDynamicSharedMemorySize, ATT_SMEM);

    wsplit_all_kernel<<<dim3(32, 32, 4), 256>>>(wq, wk, wv, wo);
    convert_kernel<<<(S_LEN * DIMV) / 1024, 256>>>(x, ah);
    gemm_qkv_kernel<<<dim3(DIMV / 128, S_LEN / 128, 3), 256, GEMM_SMEM_REQ>>>(
        ah, bq, bk, bv);
    normrope_split_kernel<<<dim3(S_LEN, 2), 256>>>(qb, kb, gq, gk, fc, fs,
                                                   qh, kh);
    attn_tc_kernel<<<dim3(SREAL / BQ, NH, 2), 128, ATT_SMEM>>>(
        qh, kh, vh, ah);
    gemm_out_kernel<<<dim3(DIMV / 128, S_LEN / 128), 256, GEMM_SMEM_REQ>>>(
        ah, bo, out);
}